// round 4
// baseline (speedup 1.0000x reference)
#include <cuda_runtime.h>
#include <cstdint>
#include <cfloat>

#define NHEAD 12
#define NB    4
#define SEQ   2048
#define HDIM  64
#define CDIM  768
#define CDIM3 2304
#define MROWS (NB*SEQ)   // 8192

// scratch (static device globals: no runtime allocation)
__device__ __align__(16) float g_q[NB*NHEAD*SEQ*HDIM];   // tf32-rounded, q pre-scaled
__device__ __align__(16) float g_k[NB*NHEAD*SEQ*HDIM];   // tf32-rounded
__device__ __align__(16) float g_v[NB*NHEAD*SEQ*HDIM];   // tf32-rounded
__device__ __align__(16) float g_y[MROWS*CDIM];          // tf32-rounded
__device__ __align__(16) float g_xr[MROWS*CDIM];         // x rounded
__device__ __align__(16) float g_wa[CDIM*CDIM3];         // W_attn rounded
__device__ __align__(16) float g_wp[CDIM*CDIM];          // W_proj rounded

__device__ __forceinline__ uint32_t f2tf(float f) {
    uint32_t u;
    asm("cvt.rna.tf32.f32 %0, %1;" : "=r"(u) : "f"(f));
    return u;
}
__device__ __forceinline__ float rnd(float f) { return __uint_as_float(f2tf(f)); }

__device__ __forceinline__ uint32_t smem_u32(const void* p) {
    uint32_t a;
    asm("{ .reg .u64 t; cvta.to.shared.u64 t, %1; cvt.u32.u64 %0, t; }"
        : "=r"(a) : "l"(p));
    return a;
}

#define CP16(dst, src) \
    asm volatile("cp.async.cg.shared.global [%0], [%1], 16;" \
                 :: "r"((uint32_t)(dst)), "l"((size_t)(src)) : "memory")
#define CP_COMMIT() asm volatile("cp.async.commit_group;" ::: "memory")
#define CP_WAIT0()  asm volatile("cp.async.wait_group 0;" ::: "memory")

__device__ __forceinline__ void mma8(float* d,
    uint32_t a0, uint32_t a1, uint32_t a2, uint32_t a3,
    uint32_t b0, uint32_t b1) {
    asm volatile(
      "mma.sync.aligned.m16n8k8.row.col.f32.tf32.tf32.f32 "
      "{%0,%1,%2,%3}, {%4,%5,%6,%7}, {%8,%9}, {%0,%1,%2,%3};\n"
      : "+f"(d[0]), "+f"(d[1]), "+f"(d[2]), "+f"(d[3])
      : "r"(a0), "r"(a1), "r"(a2), "r"(a3), "r"(b0), "r"(b1));
}

// ===================== prep: tf32-round to scratch ==========================
__global__ __launch_bounds__(256) void round4(const float* __restrict__ src,
                                              float* __restrict__ dst) {
    size_t i = ((size_t)blockIdx.x * 256 + threadIdx.x) * 4;
    float4 v = *(const float4*)(src + i);
    float4 o;
    o.x = rnd(v.x); o.y = rnd(v.y); o.z = rnd(v.z); o.w = rnd(v.w);
    *(float4*)(dst + i) = o;
}

// ===================== qkv GEMM (cp.async 2-stage) ==========================
// qkv = xr @ wa + b_attn; tile 128(M) x 64(N) x 32(K); 256 thr, warps 4x2.
#define QA_STAGE (128*36)            // words
#define QB_BASE  (2*QA_STAGE)
#define QB_STAGE (32*72)
#define QKV_SMEM ((QB_BASE + 2*QB_STAGE)*4)   // 55296 B

__global__ __launch_bounds__(256) void qkv_gemm(const float* __restrict__ bias) {
    extern __shared__ uint32_t smw[];
    uint32_t sb = smem_u32(smw);

    const int tid = threadIdx.x;
    const int wid = tid >> 5, lane = tid & 31;
    const int g = lane >> 2, tg = lane & 3;
    const int wM = wid & 3, wN = wid >> 2;
    const int rowBase = blockIdx.y * 128;
    const int colBase = blockIdx.x * 64;

    // cp.async maps
    const int arow = tid >> 1, ac0 = tid & 1;     // A: 128 rows, 2 thr/row, 4 chunks
    const int brow = tid >> 3, bc0 = tid & 7;     // B: 32 rows,  8 thr/row, 2 chunks
    const size_t asrc0 = __cvta_generic_to_global(g_xr + (size_t)(rowBase + arow)*CDIM);
    const size_t bsrc0 = __cvta_generic_to_global(g_wa + (size_t)brow*CDIM3 + colBase);
    const uint32_t adst0 = sb + arow*36*4;
    const uint32_t bdst0 = sb + (QB_BASE + brow*72)*4;

    #define QKV_ISSUE(kb, st) do { \
        size_t as_ = asrc0 + (size_t)(kb)*32*4; \
        uint32_t ad_ = adst0 + (st)*QA_STAGE*4; \
        _Pragma("unroll") \
        for (int j_ = 0; j_ < 4; j_++) CP16(ad_ + (ac0 + 2*j_)*16, as_ + (ac0 + 2*j_)*16); \
        size_t bs_ = bsrc0 + (size_t)(kb)*32*CDIM3*4; \
        uint32_t bd_ = bdst0 + (st)*QB_STAGE*4; \
        _Pragma("unroll") \
        for (int j_ = 0; j_ < 2; j_++) CP16(bd_ + (bc0 + 8*j_)*16, bs_ + (bc0 + 8*j_)*16); \
        CP_COMMIT(); \
    } while (0)

    float acc[2][4][4];
    #pragma unroll
    for (int i = 0; i < 2; i++)
        #pragma unroll
        for (int j = 0; j < 4; j++)
            #pragma unroll
            for (int e = 0; e < 4; e++) acc[i][j][e] = 0.f;

    QKV_ISSUE(0, 0);
    for (int kb = 0; kb < CDIM/32; kb++) {
        CP_WAIT0();
        __syncthreads();
        if (kb + 1 < CDIM/32) QKV_ISSUE(kb + 1, (kb + 1) & 1);

        const uint32_t* As = smw + (kb & 1)*QA_STAGE;
        const uint32_t* Bs = smw + QB_BASE + (kb & 1)*QB_STAGE;
        #pragma unroll
        for (int kk = 0; kk < 4; kk++) {
            uint32_t a[2][4], bf[4][2];
            #pragma unroll
            for (int mt = 0; mt < 2; mt++) {
                int r0 = wM*32 + mt*16 + g;
                a[mt][0] = As[ r0    *36 + kk*8 + tg];
                a[mt][1] = As[(r0+8) *36 + kk*8 + tg];
                a[mt][2] = As[ r0    *36 + kk*8 + tg + 4];
                a[mt][3] = As[(r0+8) *36 + kk*8 + tg + 4];
            }
            #pragma unroll
            for (int nt = 0; nt < 4; nt++) {
                int c0 = wN*32 + nt*8 + g;
                bf[nt][0] = Bs[(kk*8+tg  )*72 + c0];
                bf[nt][1] = Bs[(kk*8+tg+4)*72 + c0];
            }
            #pragma unroll
            for (int mt = 0; mt < 2; mt++)
                #pragma unroll
                for (int nt = 0; nt < 4; nt++)
                    mma8(acc[mt][nt], a[mt][0],a[mt][1],a[mt][2],a[mt][3],
                         bf[nt][0], bf[nt][1]);
        }
        __syncthreads();
    }

    // epilogue: one {q,k,v} x one head per 64-col block; round to tf32
    const int which = colBase / CDIM;
    const int cj = colBase % CDIM;
    const int h = cj >> 6;
    float* dst = (which == 0) ? g_q : (which == 1 ? g_k : g_v);
    const float qs = (which == 0) ? 0.125f : 1.0f;

    #pragma unroll
    for (int mt = 0; mt < 2; mt++) {
        int r0g = rowBase + wM*32 + mt*16 + g;
        int r1g = r0g + 8;
        int b0i = r0g >> 11, t0 = r0g & 2047;
        int b1i = r1g >> 11, t1 = r1g & 2047;
        size_t o0 = ((size_t)(b0i*NHEAD + h)*SEQ + t0)*HDIM;
        size_t o1 = ((size_t)(b1i*NHEAD + h)*SEQ + t1)*HDIM;
        #pragma unroll
        for (int nt = 0; nt < 4; nt++) {
            int d0 = wN*32 + nt*8 + tg*2;
            float bb0 = bias[colBase + d0];
            float bb1 = bias[colBase + d0 + 1];
            dst[o0 + d0    ] = rnd((acc[mt][nt][0] + bb0) * qs);
            dst[o0 + d0 + 1] = rnd((acc[mt][nt][1] + bb1) * qs);
            dst[o1 + d0    ] = rnd((acc[mt][nt][2] + bb0) * qs);
            dst[o1 + d0 + 1] = rnd((acc[mt][nt][3] + bb1) * qs);
        }
    }
}

// ===================== flash attention (cp.async 2-stage) ===================
#define KSW 68
#define VSW 72
#define KS_STAGE (64*KSW)
#define VS_STAGE (64*VSW)
#define VS_BASE  (2*KS_STAGE)
#define PB_BASE  (VS_BASE + 2*VS_STAGE)
#define FLASH_SMEM ((PB_BASE + 128*KSW)*4)    // 106496 B

__global__ __launch_bounds__(256, 2) void flash_attn(const float* __restrict__ mask) {
    extern __shared__ uint32_t sm[];
    uint32_t sb = smem_u32(sm);

    const int tid = threadIdx.x;
    const int wid = tid >> 5, lane = tid & 31;
    const int g = lane >> 2, tg = lane & 3;
    const int qt = (int)(gridDim.x - 1 - blockIdx.x);   // heavy tiles first
    const int h = blockIdx.y >> 2, b = blockIdx.y & 3;
    const int rw = wid * 16;

    const float* Qg  = g_q + ((size_t)((b*NHEAD + h)*SEQ) + qt*128)*HDIM;
    const float* Kg0 = g_k + (size_t)((b*NHEAD + h)*SEQ)*HDIM;
    const float* Vg0 = g_v + (size_t)((b*NHEAD + h)*SEQ)*HDIM;
    const float* Mb  = mask + ((size_t)h*SEQ + qt*128)*SEQ;

    // cp.async map: 64 rows, 4 thr/row, 4x16B chunks each
    const int crow = tid >> 2, cc0 = tid & 3;
    const size_t ksrc0 = __cvta_generic_to_global(Kg0 + (size_t)crow*HDIM);
    const size_t vsrc0 = __cvta_generic_to_global(Vg0 + (size_t)crow*HDIM);
    const uint32_t kdst0 = sb + crow*KSW*4;
    const uint32_t vdst0 = sb + (VS_BASE + crow*VSW)*4;

    #define KV_ISSUE(kt, st) do { \
        size_t ks_ = ksrc0 + (size_t)(kt)*64*HDIM*4; \
        size_t vs_ = vsrc0 + (size_t)(kt)*64*HDIM*4; \
        uint32_t kd_ = kdst0 + (st)*KS_STAGE*4; \
        uint32_t vd_ = vdst0 + (st)*VS_STAGE*4; \
        _Pragma("unroll") \
        for (int j_ = 0; j_ < 4; j_++) { \
            CP16(kd_ + (cc0 + 4*j_)*16, ks_ + (cc0 + 4*j_)*16); \
            CP16(vd_ + (cc0 + 4*j_)*16, vs_ + (cc0 + 4*j_)*16); \
        } \
        CP_COMMIT(); \
    } while (0)

    KV_ISSUE(0, 0);

    // Q fragments (pre-rounded, pre-scaled) held in registers all block
    uint32_t qa[8][4];
    #pragma unroll
    for (int kk = 0; kk < 8; kk++) {
        qa[kk][0] = __float_as_uint(Qg[(rw+g  )*HDIM + kk*8 + tg]);
        qa[kk][1] = __float_as_uint(Qg[(rw+8+g)*HDIM + kk*8 + tg]);
        qa[kk][2] = __float_as_uint(Qg[(rw+g  )*HDIM + kk*8 + tg + 4]);
        qa[kk][3] = __float_as_uint(Qg[(rw+8+g)*HDIM + kk*8 + tg + 4]);
    }

    float o[8][4];
    #pragma unroll
    for (int nt = 0; nt < 8; nt++)
        #pragma unroll
        for (int e = 0; e < 4; e++) o[nt][e] = 0.f;
    float m0 = -FLT_MAX, m1 = -FLT_MAX, l0 = 0.f, l1 = 0.f;

    const int ktEnd = 2*qt + 1;
    for (int kt = 0; kt <= ktEnd; kt++) {
        CP_WAIT0();
        __syncthreads();
        if (kt < ktEnd) KV_ISSUE(kt + 1, (kt + 1) & 1);

        const uint32_t* Ks = sm + (kt & 1)*KS_STAGE;
        const uint32_t* Vs = sm + VS_BASE + (kt & 1)*VS_STAGE;
        uint32_t* Pb = sm + PB_BASE;

        // seed S accumulators with the additive mask (QK^T added on top)
        float s[8][4];
        const float* M0 = Mb + (size_t)(rw+g)*SEQ + kt*64;
        const float* M1 = M0 + (size_t)8*SEQ;
        #pragma unroll
        for (int nt = 0; nt < 8; nt++) {
            float2 u = *(const float2*)(M0 + nt*8 + tg*2);
            float2 w = *(const float2*)(M1 + nt*8 + tg*2);
            s[nt][0] = u.x; s[nt][1] = u.y;
            s[nt][2] = w.x; s[nt][3] = w.y;
        }

        // S = mask + Q K^T
        #pragma unroll
        for (int kk = 0; kk < 8; kk++) {
            #pragma unroll
            for (int nt = 0; nt < 8; nt++) {
                uint32_t b0 = Ks[(nt*8+g)*KSW + kk*8 + tg];
                uint32_t b1 = Ks[(nt*8+g)*KSW + kk*8 + tg + 4];
                mma8(s[nt], qa[kk][0], qa[kk][1], qa[kk][2], qa[kk][3], b0, b1);
            }
        }

        // online softmax (warp-local rows)
        float rm0 = -FLT_MAX, rm1 = -FLT_MAX;
        #pragma unroll
        for (int nt = 0; nt < 8; nt++) {
            rm0 = fmaxf(rm0, fmaxf(s[nt][0], s[nt][1]));
            rm1 = fmaxf(rm1, fmaxf(s[nt][2], s[nt][3]));
        }
        rm0 = fmaxf(rm0, __shfl_xor_sync(0xffffffffu, rm0, 1));
        rm0 = fmaxf(rm0, __shfl_xor_sync(0xffffffffu, rm0, 2));
        rm1 = fmaxf(rm1, __shfl_xor_sync(0xffffffffu, rm1, 1));
        rm1 = fmaxf(rm1, __shfl_xor_sync(0xffffffffu, rm1, 2));

        float mn0 = fmaxf(m0, rm0), mn1 = fmaxf(m1, rm1);
        float f0 = __expf(m0 - mn0), f1 = __expf(m1 - mn1);
        m0 = mn0; m1 = mn1;

        float rs0 = 0.f, rs1 = 0.f;
        #pragma unroll
        for (int nt = 0; nt < 8; nt++) {
            s[nt][0] = __expf(s[nt][0] - mn0);
            s[nt][1] = __expf(s[nt][1] - mn0);
            s[nt][2] = __expf(s[nt][2] - mn1);
            s[nt][3] = __expf(s[nt][3] - mn1);
            rs0 += s[nt][0] + s[nt][1];
            rs1 += s[nt][2] + s[nt][3];
        }
        l0 = l0*f0 + rs0;
        l1 = l1*f1 + rs1;
        #pragma unroll
        for (int nt = 0; nt < 8; nt++) {
            o[nt][0] *= f0; o[nt][1] *= f0;
            o[nt][2] *= f1; o[nt][3] *= f1;
        }

        // P -> warp-local smem (C-frag -> A-frag layout change)
        #pragma unroll
        for (int nt = 0; nt < 8; nt++) {
            int c = nt*8 + tg*2;
            Pb[(rw+g  )*KSW + c    ] = f2tf(s[nt][0]);
            Pb[(rw+g  )*KSW + c + 1] = f2tf(s[nt][1]);
            Pb[(rw+8+g)*KSW + c    ] = f2tf(s[nt][2]);
            Pb[(rw+8+g)*KSW + c + 1] = f2tf(s[nt][3]);
        }
        __syncwarp();

        // O += P V
        #pragma unroll
        for (int kk = 0; kk < 8; kk++) {
            uint32_t a0 = Pb[(rw+g  )*KSW + kk*8 + tg];
            uint32_t a1 = Pb[(rw+8+g)*KSW + kk*8 + tg];
            uint32_t a2 = Pb[(rw+g  )*KSW + kk*8 + tg + 4];
            uint32_t a3 = Pb[(rw+8+g)*KSW + kk*8 + tg + 4];
            #pragma unroll
            for (int nt = 0; nt < 8; nt++) {
                uint32_t b0 = Vs[(kk*8+tg  )*VSW + nt*8 + g];
                uint32_t b1 = Vs[(kk*8+tg+4)*VSW + nt*8 + g];
                mma8(o[nt], a0, a1, a2, a3, b0, b1);
            }
        }
    }

    // finalize; write tf32-rounded y (proj consumes raw via cp.async)
    l0 += __shfl_xor_sync(0xffffffffu, l0, 1);
    l0 += __shfl_xor_sync(0xffffffffu, l0, 2);
    l1 += __shfl_xor_sync(0xffffffffu, l1, 1);
    l1 += __shfl_xor_sync(0xffffffffu, l1, 2);
    float inv0 = 1.f / l0, inv1 = 1.f / l1;

    int r0 = qt*128 + rw + g, r1 = r0 + 8;
    float* y0 = g_y + (size_t)(b*SEQ + r0)*CDIM + h*HDIM;
    float* y1 = g_y + (size_t)(b*SEQ + r1)*CDIM + h*HDIM;
    #pragma unroll
    for (int nt = 0; nt < 8; nt++) {
        int c = nt*8 + tg*2;
        y0[c]   = rnd(o[nt][0]*inv0);  y0[c+1] = rnd(o[nt][1]*inv0);
        y1[c]   = rnd(o[nt][2]*inv1);  y1[c+1] = rnd(o[nt][3]*inv1);
    }
}

// ===================== proj GEMM (cp.async 2-stage) =========================
__global__ __launch_bounds__(256) void proj_gemm(const float* __restrict__ bias,
                                                 float* __restrict__ out) {
    extern __shared__ uint32_t smw[];
    uint32_t sb = smem_u32(smw);

    const int tid = threadIdx.x;
    const int wid = tid >> 5, lane = tid & 31;
    const int g = lane >> 2, tg = lane & 3;
    const int wM = wid & 3, wN = wid >> 2;
    const int rowBase = blockIdx.y * 128;
    const int colBase = blockIdx.x * 64;

    const int arow = tid >> 1, ac0 = tid & 1;
    const int brow = tid >> 3, bc0 = tid & 7;
    const size_t asrc0 = __cvta_generic_to_global(g_y + (size_t)(rowBase + arow)*CDIM);
    const size_t bsrc0 = __cvta_generic_to_global(g_wp + (size_t)brow*CDIM + colBase);
    const uint32_t adst0 = sb + arow*36*4;
    const uint32_t bdst0 = sb + (QB_BASE + brow*72)*4;

    #define PRJ_ISSUE(kb, st) do { \
        size_t as_ = asrc0 + (size_t)(kb)*32*4; \
        uint32_t ad_ = adst0 + (st)*QA_STAGE*4; \
        _Pragma("unroll") \
        for (int j_ = 0; j_ < 4; j_++) CP16(ad_ + (ac0 + 2*j_)*16, as_ + (ac0 + 2*j_)*16); \
        size_t bs_ = bsrc0 + (size_t)(kb)*32*CDIM*4; \
        uint32_t bd_ = bdst0 + (st)*QB_STAGE*4; \
        _Pragma("unroll") \
        for (int j_ = 0; j_ < 2; j_++) CP16(bd_ + (bc0 + 8*j_)*16, bs_ + (bc0 + 8*j_)*16); \
        CP_COMMIT(); \
    } while (0)

    float acc[2][4][4];
    #pragma unroll
    for (int i = 0; i < 2; i++)
        #pragma unroll
        for (int j = 0; j < 4; j++)
            #pragma unroll
            for (int e = 0; e < 4; e++) acc[i][j][e] = 0.f;

    PRJ_ISSUE(0, 0);
    for (int kb = 0; kb < CDIM/32; kb++) {
        CP_WAIT0();
        __syncthreads();
        if (kb + 1 < CDIM/32) PRJ_ISSUE(kb + 1, (kb + 1) & 1);

        const uint32_t* As = smw + (kb & 1)*QA_STAGE;
        const uint32_t* Bs = smw + QB_BASE + (kb & 1)*QB_STAGE;
        #pragma unroll
        for (int kk = 0; kk < 4; kk++) {
            uint32_t a[2][4], bf[4][2];
            #pragma unroll
            for (int mt = 0; mt < 2; mt++) {
                int r0 = wM*32 + mt*16 + g;
                a[mt][0] = As[ r0    *36 + kk*8 + tg];
                a[mt][1] = As[(r0+8) *36 + kk*8 + tg];
                a[mt][2] = As[ r0    *36 + kk*8 + tg + 4];
                a[mt][3] = As[(r0+8) *36 + kk*8 + tg + 4];
            }
            #pragma unroll
            for (int nt = 0; nt < 4; nt++) {
                int c0 = wN*32 + nt*8 + g;
                bf[nt][0] = Bs[(kk*8+tg  )*72 + c0];
                bf[nt][1] = Bs[(kk*8+tg+4)*72 + c0];
            }
            #pragma unroll
            for (int mt = 0; mt < 2; mt++)
                #pragma unroll
                for (int nt = 0; nt < 4; nt++)
                    mma8(acc[mt][nt], a[mt][0],a[mt][1],a[mt][2],a[mt][3],
                         bf[nt][0], bf[nt][1]);
        }
        __syncthreads();
    }

    #pragma unroll
    for (int mt = 0; mt < 2; mt++) {
        int r0g = rowBase + wM*32 + mt*16 + g;
        int r1g = r0g + 8;
        #pragma unroll
        for (int nt = 0; nt < 4; nt++) {
            int j = colBase + wN*32 + nt*8 + tg*2;
            float bb0 = bias[j], bb1 = bias[j+1];
            out[(size_t)r0g*CDIM + j    ] = acc[mt][nt][0] + bb0;
            out[(size_t)r0g*CDIM + j + 1] = acc[mt][nt][1] + bb1;
            out[(size_t)r1g*CDIM + j    ] = acc[mt][nt][2] + bb0;
            out[(size_t)r1g*CDIM + j + 1] = acc[mt][nt][3] + bb1;
        }
    }
}

// ===================== host =================================================
extern "C" void kernel_launch(void* const* d_in, const int* in_sizes, int n_in,
                              void* d_out, int out_size) {
    const float* x      = (const float*)d_in[0];
    const float* mask   = (const float*)d_in[1];
    const float* W_attn = (const float*)d_in[2];
    const float* b_attn = (const float*)d_in[3];
    const float* W_proj = (const float*)d_in[4];
    const float* b_proj = (const float*)d_in[5];
    float* out = (float*)d_out;

    void *p_xr, *p_wa, *p_wp;
    cudaGetSymbolAddress(&p_xr, g_xr);
    cudaGetSymbolAddress(&p_wa, g_wa);
    cudaGetSymbolAddress(&p_wp, g_wp);

    cudaFuncSetAttribute((const void*)qkv_gemm,
                         cudaFuncAttributeMaxDynamicSharedMemorySize, QKV_SMEM);
    cudaFuncSetAttribute((const void*)proj_gemm,
                         cudaFuncAttributeMaxDynamicSharedMemorySize, QKV_SMEM);
    cudaFuncSetAttribute((const void*)flash_attn,
                         cudaFuncAttributeMaxDynamicSharedMemorySize, FLASH_SMEM);

    // prep: tf32-round inputs once
    round4<<<(MROWS*CDIM/4)/256, 256>>>(x, (float*)p_xr);
    round4<<<(CDIM*CDIM3/4)/256, 256>>>(W_attn, (float*)p_wa);
    round4<<<(CDIM*CDIM/4)/256, 256>>>(W_proj, (float*)p_wp);

    dim3 g1(CDIM3/64, MROWS/128);      // 36 x 64
    qkv_gemm<<<g1, 256, QKV_SMEM>>>(b_attn);

    dim3 g2(SEQ/128, NHEAD*NB);        // 16 x 48 (h-major: mask L2 reuse over b)
    flash_attn<<<g2, 256, FLASH_SMEM>>>(mask);

    dim3 g3(CDIM/64, MROWS/128);       // 12 x 64
    proj_gemm<<<g3, 256, QKV_SMEM>>>(b_proj, out);
}

// round 5
// speedup vs baseline: 1.1559x; 1.1559x over previous
#include <cuda_runtime.h>
#include <cstdint>
#include <cfloat>

#define NHEAD 12
#define NB    4
#define SEQ   2048
#define HDIM  64
#define CDIM  768
#define CDIM3 2304
#define MROWS (NB*SEQ)   // 8192

// scratch (static device globals: no runtime allocation)
__device__ __align__(16) float g_q[NB*NHEAD*SEQ*HDIM];   // tf32-rounded, q pre-scaled
__device__ __align__(16) float g_k[NB*NHEAD*SEQ*HDIM];   // tf32-rounded
__device__ __align__(16) float g_v[NB*NHEAD*SEQ*HDIM];   // tf32-rounded
__device__ __align__(16) float g_y[MROWS*CDIM];

__device__ __forceinline__ uint32_t f2tf(float f) {
    uint32_t u;
    asm("cvt.rna.tf32.f32 %0, %1;" : "=r"(u) : "f"(f));
    return u;
}
__device__ __forceinline__ float rnd(float f) { return __uint_as_float(f2tf(f)); }

__device__ __forceinline__ uint32_t smem_u32(const void* p) {
    uint32_t a;
    asm("{ .reg .u64 t; cvta.to.shared.u64 t, %1; cvt.u32.u64 %0, t; }"
        : "=r"(a) : "l"(p));
    return a;
}

#define CP16(dst, src) \
    asm volatile("cp.async.cg.shared.global [%0], [%1], 16;" \
                 :: "r"((uint32_t)(dst)), "l"((size_t)(src)) : "memory")
#define CP_COMMIT() asm volatile("cp.async.commit_group;" ::: "memory")
#define CP_WAIT0()  asm volatile("cp.async.wait_group 0;" ::: "memory")

__device__ __forceinline__ void mma8(float* d,
    uint32_t a0, uint32_t a1, uint32_t a2, uint32_t a3,
    uint32_t b0, uint32_t b1) {
    asm volatile(
      "mma.sync.aligned.m16n8k8.row.col.f32.tf32.tf32.f32 "
      "{%0,%1,%2,%3}, {%4,%5,%6,%7}, {%8,%9}, {%0,%1,%2,%3};\n"
      : "+f"(d[0]), "+f"(d[1]), "+f"(d[2]), "+f"(d[3])
      : "r"(a0), "r"(a1), "r"(a2), "r"(a3), "r"(b0), "r"(b1));
}

// ---------------------------------------------------------------------------
// Kernel 1: qkv = x @ W_attn + b_attn (R1-proven tiling: LDG+cvt+STS, L1 reuse)
// Epilogue writes tf32-rounded q/k/v, q pre-scaled by 0.125.
// ---------------------------------------------------------------------------
__global__ __launch_bounds__(256) void qkv_gemm(
    const float* __restrict__ x, const float* __restrict__ W,
    const float* __restrict__ bias) {
    __shared__ uint32_t As[128*36];
    __shared__ uint32_t Bs[32*72];

    const int tid = threadIdx.x;
    const int wid = tid >> 5, lane = tid & 31;
    const int g = lane >> 2, tg = lane & 3;
    const int wM = wid & 3, wN = wid >> 2;
    const int rowBase = blockIdx.y * 128;
    const int colBase = blockIdx.x * 64;

    float acc[2][4][4];
    #pragma unroll
    for (int i = 0; i < 2; i++)
        #pragma unroll
        for (int j = 0; j < 4; j++)
            #pragma unroll
            for (int e = 0; e < 4; e++) acc[i][j][e] = 0.f;

    for (int kb = 0; kb < CDIM/32; kb++) {
        #pragma unroll
        for (int r = 0; r < 4; r++) {
            int m  = (tid >> 3) + r*32;
            int k4 = (tid & 7) * 4;
            float4 v = *(const float4*)(x + (size_t)(rowBase+m)*CDIM + kb*32 + k4);
            uint32_t* p = &As[m*36 + k4];
            p[0]=f2tf(v.x); p[1]=f2tf(v.y); p[2]=f2tf(v.z); p[3]=f2tf(v.w);
        }
        #pragma unroll
        for (int r = 0; r < 2; r++) {
            int k  = (tid >> 4) + r*16;
            int n4 = (tid & 15) * 4;
            float4 v = *(const float4*)(W + (size_t)(kb*32+k)*CDIM3 + colBase + n4);
            uint32_t* p = &Bs[k*72 + n4];
            p[0]=f2tf(v.x); p[1]=f2tf(v.y); p[2]=f2tf(v.z); p[3]=f2tf(v.w);
        }
        __syncthreads();
        #pragma unroll
        for (int kk = 0; kk < 4; kk++) {
            uint32_t a[2][4], bf[4][2];
            #pragma unroll
            for (int mt = 0; mt < 2; mt++) {
                int r0 = wM*32 + mt*16 + g;
                a[mt][0] = As[ r0     *36 + kk*8 + tg];
                a[mt][1] = As[(r0+8)  *36 + kk*8 + tg];
                a[mt][2] = As[ r0     *36 + kk*8 + tg + 4];
                a[mt][3] = As[(r0+8)  *36 + kk*8 + tg + 4];
            }
            #pragma unroll
            for (int nt = 0; nt < 4; nt++) {
                int c0 = wN*32 + nt*8 + g;
                bf[nt][0] = Bs[(kk*8+tg  )*72 + c0];
                bf[nt][1] = Bs[(kk*8+tg+4)*72 + c0];
            }
            #pragma unroll
            for (int mt = 0; mt < 2; mt++)
                #pragma unroll
                for (int nt = 0; nt < 4; nt++)
                    mma8(acc[mt][nt], a[mt][0],a[mt][1],a[mt][2],a[mt][3],
                         bf[nt][0], bf[nt][1]);
        }
        __syncthreads();
    }

    const int which = colBase / CDIM;
    const int cj = colBase % CDIM;
    const int h = cj >> 6;
    float* dst = (which == 0) ? g_q : (which == 1 ? g_k : g_v);
    const float qs = (which == 0) ? 0.125f : 1.0f;

    #pragma unroll
    for (int mt = 0; mt < 2; mt++) {
        int r0g = rowBase + wM*32 + mt*16 + g;
        int r1g = r0g + 8;
        int b0i = r0g >> 11, t0 = r0g & 2047;
        int b1i = r1g >> 11, t1 = r1g & 2047;
        size_t o0 = ((size_t)(b0i*NHEAD + h)*SEQ + t0)*HDIM;
        size_t o1 = ((size_t)(b1i*NHEAD + h)*SEQ + t1)*HDIM;
        #pragma unroll
        for (int nt = 0; nt < 4; nt++) {
            int d0 = wN*32 + nt*8 + tg*2;
            float bb0 = bias[colBase + d0];
            float bb1 = bias[colBase + d0 + 1];
            dst[o0 + d0    ] = rnd((acc[mt][nt][0] + bb0) * qs);
            dst[o0 + d0 + 1] = rnd((acc[mt][nt][1] + bb1) * qs);
            dst[o1 + d0    ] = rnd((acc[mt][nt][2] + bb0) * qs);
            dst[o1 + d0 + 1] = rnd((acc[mt][nt][3] + bb1) * qs);
        }
    }
}

// ---------------------------------------------------------------------------
// Kernel 2: flash attention. cp.async double-buffered K/V; mask LDGs issued
// into the S accumulators BEFORE waiting on K/V (latency hides under wait);
// S-MMA nt-outer so each accumulator chain starts when its mask words land.
// ---------------------------------------------------------------------------
#define KSW 68
#define VSW 72
#define KS_STAGE (64*KSW)
#define VS_STAGE (64*VSW)
#define VS_BASE  (2*KS_STAGE)
#define PB_BASE  (VS_BASE + 2*VS_STAGE)
#define FLASH_SMEM ((PB_BASE + 128*KSW)*4)    // 106496 B

__global__ __launch_bounds__(256, 2) void flash_attn(const float* __restrict__ mask) {
    extern __shared__ uint32_t sm[];
    uint32_t sb = smem_u32(sm);

    const int tid = threadIdx.x;
    const int wid = tid >> 5, lane = tid & 31;
    const int g = lane >> 2, tg = lane & 3;
    const int qt = (int)(gridDim.x - 1 - blockIdx.x);   // heavy tiles first
    const int h = blockIdx.y >> 2, b = blockIdx.y & 3;
    const int rw = wid * 16;

    const float* Qg  = g_q + ((size_t)((b*NHEAD + h)*SEQ) + qt*128)*HDIM;
    const float* Kg0 = g_k + (size_t)((b*NHEAD + h)*SEQ)*HDIM;
    const float* Vg0 = g_v + (size_t)((b*NHEAD + h)*SEQ)*HDIM;
    const float* Mb  = mask + ((size_t)h*SEQ + qt*128)*SEQ;

    const int crow = tid >> 2, cc0 = tid & 3;
    const size_t ksrc0 = __cvta_generic_to_global(Kg0 + (size_t)crow*HDIM);
    const size_t vsrc0 = __cvta_generic_to_global(Vg0 + (size_t)crow*HDIM);
    const uint32_t kdst0 = sb + crow*KSW*4;
    const uint32_t vdst0 = sb + (VS_BASE + crow*VSW)*4;

    #define KV_ISSUE(kt, st) do { \
        size_t ks_ = ksrc0 + (size_t)(kt)*64*HDIM*4; \
        size_t vs_ = vsrc0 + (size_t)(kt)*64*HDIM*4; \
        uint32_t kd_ = kdst0 + (st)*KS_STAGE*4; \
        uint32_t vd_ = vdst0 + (st)*VS_STAGE*4; \
        _Pragma("unroll") \
        for (int j_ = 0; j_ < 4; j_++) { \
            CP16(kd_ + (cc0 + 4*j_)*16, ks_ + (cc0 + 4*j_)*16); \
            CP16(vd_ + (cc0 + 4*j_)*16, vs_ + (cc0 + 4*j_)*16); \
        } \
        CP_COMMIT(); \
    } while (0)

    KV_ISSUE(0, 0);

    // Q fragments (pre-rounded, pre-scaled) in registers for the whole block
    uint32_t qa[8][4];
    #pragma unroll
    for (int kk = 0; kk < 8; kk++) {
        qa[kk][0] = __float_as_uint(Qg[(rw+g  )*HDIM + kk*8 + tg]);
        qa[kk][1] = __float_as_uint(Qg[(rw+8+g)*HDIM + kk*8 + tg]);
        qa[kk][2] = __float_as_uint(Qg[(rw+g  )*HDIM + kk*8 + tg + 4]);
        qa[kk][3] = __float_as_uint(Qg[(rw+8+g)*HDIM + kk*8 + tg + 4]);
    }

    float o[8][4];
    #pragma unroll
    for (int nt = 0; nt < 8; nt++)
        #pragma unroll
        for (int e = 0; e < 4; e++) o[nt][e] = 0.f;
    float m0 = -FLT_MAX, m1 = -FLT_MAX, l0 = 0.f, l1 = 0.f;

    const int ktEnd = 2*qt + 1;
    for (int kt = 0; kt <= ktEnd; kt++) {
        // mask -> S accumulators; LDGs issued BEFORE waiting on K/V stage
        float s[8][4];
        const float* M0 = Mb + (size_t)(rw+g)*SEQ + kt*64;
        const float* M1 = M0 + (size_t)8*SEQ;
        #pragma unroll
        for (int nt = 0; nt < 8; nt++) {
            float2 u = *(const float2*)(M0 + nt*8 + tg*2);
            float2 w = *(const float2*)(M1 + nt*8 + tg*2);
            s[nt][0] = u.x; s[nt][1] = u.y;
            s[nt][2] = w.x; s[nt][3] = w.y;
        }

        CP_WAIT0();
        __syncthreads();
        if (kt < ktEnd) KV_ISSUE(kt + 1, (kt + 1) & 1);

        const uint32_t* Ks = sm + (kt & 1)*KS_STAGE;
        const uint32_t* Vs = sm + VS_BASE + (kt & 1)*VS_STAGE;
        uint32_t* Pb = sm + PB_BASE;

        // S = mask + Q K^T  (nt-outer: each chain gated only by its own mask)
        #pragma unroll
        for (int nt = 0; nt < 8; nt++) {
            #pragma unroll
            for (int kk = 0; kk < 8; kk++) {
                uint32_t b0 = Ks[(nt*8+g)*KSW + kk*8 + tg];
                uint32_t b1 = Ks[(nt*8+g)*KSW + kk*8 + tg + 4];
                mma8(s[nt], qa[kk][0], qa[kk][1], qa[kk][2], qa[kk][3], b0, b1);
            }
        }

        // online softmax (warp-local rows)
        float rm0 = -FLT_MAX, rm1 = -FLT_MAX;
        #pragma unroll
        for (int nt = 0; nt < 8; nt++) {
            rm0 = fmaxf(rm0, fmaxf(s[nt][0], s[nt][1]));
            rm1 = fmaxf(rm1, fmaxf(s[nt][2], s[nt][3]));
        }
        rm0 = fmaxf(rm0, __shfl_xor_sync(0xffffffffu, rm0, 1));
        rm0 = fmaxf(rm0, __shfl_xor_sync(0xffffffffu, rm0, 2));
        rm1 = fmaxf(rm1, __shfl_xor_sync(0xffffffffu, rm1, 1));
        rm1 = fmaxf(rm1, __shfl_xor_sync(0xffffffffu, rm1, 2));

        float mn0 = fmaxf(m0, rm0), mn1 = fmaxf(m1, rm1);
        float f0 = __expf(m0 - mn0), f1 = __expf(m1 - mn1);
        m0 = mn0; m1 = mn1;

        float rs0 = 0.f, rs1 = 0.f;
        #pragma unroll
        for (int nt = 0; nt < 8; nt++) {
            s[nt][0] = __expf(s[nt][0] - mn0);
            s[nt][1] = __expf(s[nt][1] - mn0);
            s[nt][2] = __expf(s[nt][2] - mn1);
            s[nt][3] = __expf(s[nt][3] - mn1);
            rs0 += s[nt][0] + s[nt][1];
            rs1 += s[nt][2] + s[nt][3];
        }
        l0 = l0*f0 + rs0;
        l1 = l1*f1 + rs1;
        #pragma unroll
        for (int nt = 0; nt < 8; nt++) {
            o[nt][0] *= f0; o[nt][1] *= f0;
            o[nt][2] *= f1; o[nt][3] *= f1;
        }

        // P -> warp-local smem (C-frag -> A-frag layout change)
        #pragma unroll
        for (int nt = 0; nt < 8; nt++) {
            int c = nt*8 + tg*2;
            Pb[(rw+g  )*KSW + c    ] = f2tf(s[nt][0]);
            Pb[(rw+g  )*KSW + c + 1] = f2tf(s[nt][1]);
            Pb[(rw+8+g)*KSW + c    ] = f2tf(s[nt][2]);
            Pb[(rw+8+g)*KSW + c + 1] = f2tf(s[nt][3]);
        }
        __syncwarp();

        // O += P V
        #pragma unroll
        for (int kk = 0; kk < 8; kk++) {
            uint32_t a0 = Pb[(rw+g  )*KSW + kk*8 + tg];
            uint32_t a1 = Pb[(rw+8+g)*KSW + kk*8 + tg];
            uint32_t a2 = Pb[(rw+g  )*KSW + kk*8 + tg + 4];
            uint32_t a3 = Pb[(rw+8+g)*KSW + kk*8 + tg + 4];
            #pragma unroll
            for (int nt = 0; nt < 8; nt++) {
                uint32_t b0 = Vs[(kk*8+tg  )*VSW + nt*8 + g];
                uint32_t b1 = Vs[(kk*8+tg+4)*VSW + nt*8 + g];
                mma8(o[nt], a0, a1, a2, a3, b0, b1);
            }
        }
    }

    l0 += __shfl_xor_sync(0xffffffffu, l0, 1);
    l0 += __shfl_xor_sync(0xffffffffu, l0, 2);
    l1 += __shfl_xor_sync(0xffffffffu, l1, 1);
    l1 += __shfl_xor_sync(0xffffffffu, l1, 2);
    float inv0 = 1.f / l0, inv1 = 1.f / l1;

    int r0 = qt*128 + rw + g, r1 = r0 + 8;
    float* y0 = g_y + (size_t)(b*SEQ + r0)*CDIM + h*HDIM;
    float* y1 = g_y + (size_t)(b*SEQ + r1)*CDIM + h*HDIM;
    #pragma unroll
    for (int nt = 0; nt < 8; nt++) {
        int c = nt*8 + tg*2;
        y0[c]   = o[nt][0]*inv0;  y0[c+1] = o[nt][1]*inv0;
        y1[c]   = o[nt][2]*inv1;  y1[c+1] = o[nt][3]*inv1;
    }
}

// ---------------------------------------------------------------------------
// Kernel 3: out = y @ W_proj + b_proj  (R1-proven tiling)
// ---------------------------------------------------------------------------
__global__ __launch_bounds__(256) void proj_gemm(
    const float* __restrict__ W, const float* __restrict__ bias,
    float* __restrict__ out) {
    __shared__ uint32_t As[128*36];
    __shared__ uint32_t Bs[32*72];

    const int tid = threadIdx.x;
    const int wid = tid >> 5, lane = tid & 31;
    const int g = lane >> 2, tg = lane & 3;
    const int wM = wid & 3, wN = wid >> 2;
    const int rowBase = blockIdx.y * 128;
    const int colBase = blockIdx.x * 64;
    const float* A = g_y;

    float acc[2][4][4];
    #pragma unroll
    for (int i = 0; i < 2; i++)
        #pragma unroll
        for (int j = 0; j < 4; j++)
            #pragma unroll
            for (int e = 0; e < 4; e++) acc[i][j][e] = 0.f;

    for (int kb = 0; kb < CDIM/32; kb++) {
        #pragma unroll
        for (int r = 0; r < 4; r++) {
            int m  = (tid >> 3) + r*32;
            int k4 = (tid & 7) * 4;
            float4 v = *(const float4*)(A + (size_t)(rowBase+m)*CDIM + kb*32 + k4);
            uint32_t* p = &As[m*36 + k4];
            p[0]=f2tf(v.x); p[1]=f2tf(v.y); p[2]=f2tf(v.z); p[3]=f2tf(v.w);
        }
        #pragma unroll
        for (int r = 0; r < 2; r++) {
            int k  = (tid >> 4) + r*16;
            int n4 = (tid & 15) * 4;
            float4 v = *(const float4*)(W + (size_t)(kb*32+k)*CDIM + colBase + n4);
            uint32_t* p = &Bs[k*72 + n4];
            p[0]=f2tf(v.x); p[1]=f2tf(v.y); p[2]=f2tf(v.z); p[3]=f2tf(v.w);
        }
        __syncthreads();
        #pragma unroll
        for (int kk = 0; kk < 4; kk++) {
            uint32_t a[2][4], bf[4][2];
            #pragma unroll
            for (int mt = 0; mt < 2; mt++) {
                int r0 = wM*32 + mt*16 + g;
                a[mt][0] = As[ r0    *36 + kk*8 + tg];
                a[mt][1] = As[(r0+8) *36 + kk*8 + tg];
                a[mt][2] = As[ r0    *36 + kk*8 + tg + 4];
                a[mt][3] = As[(r0+8) *36 + kk*8 + tg + 4];
            }
            #pragma unroll
            for (int nt = 0; nt < 4; nt++) {
                int c0 = wN*32 + nt*8 + g;
                bf[nt][0] = Bs[(kk*8+tg  )*72 + c0];
                bf[nt][1] = Bs[(kk*8+tg+4)*72 + c0];
            }
            #pragma unroll
            for (int mt = 0; mt < 2; mt++)
                #pragma unroll
                for (int nt = 0; nt < 4; nt++)
                    mma8(acc[mt][nt], a[mt][0],a[mt][1],a[mt][2],a[mt][3],
                         bf[nt][0], bf[nt][1]);
        }
        __syncthreads();
    }

    #pragma unroll
    for (int mt = 0; mt < 2; mt++) {
        int r0g = rowBase + wM*32 + mt*16 + g;
        int r1g = r0g + 8;
        #pragma unroll
        for (int nt = 0; nt < 4; nt++) {
            int j = colBase + wN*32 + nt*8 + tg*2;
            float bb0 = bias[j], bb1 = bias[j+1];
            out[(size_t)r0g*CDIM + j    ] = acc[mt][nt][0] + bb0;
            out[(size_t)r0g*CDIM + j + 1] = acc[mt][nt][1] + bb1;
            out[(size_t)r1g*CDIM + j    ] = acc[mt][nt][2] + bb0;
            out[(size_t)r1g*CDIM + j + 1] = acc[mt][nt][3] + bb1;
        }
    }
}

extern "C" void kernel_launch(void* const* d_in, const int* in_sizes, int n_in,
                              void* d_out, int out_size) {
    const float* x      = (const float*)d_in[0];
    const float* mask   = (const float*)d_in[1];
    const float* W_attn = (const float*)d_in[2];
    const float* b_attn = (const float*)d_in[3];
    const float* W_proj = (const float*)d_in[4];
    const float* b_proj = (const float*)d_in[5];
    float* out = (float*)d_out;

    cudaFuncSetAttribute((const void*)flash_attn,
                         cudaFuncAttributeMaxDynamicSharedMemorySize, FLASH_SMEM);

    dim3 g1(CDIM3/64, MROWS/128);      // 36 x 64
    qkv_gemm<<<g1, 256>>>(x, W_attn, b_attn);

    dim3 g2(SEQ/128, NHEAD*NB);        // 16 x 48 (h-major: mask L2 reuse over b)
    flash_attn<<<g2, 256, FLASH_SMEM>>>(mask);

    dim3 g3(CDIM/64, MROWS/128);       // 12 x 64
    proj_gemm<<<g3, 256>>>(W_proj, b_proj, out);
}

// round 6
// speedup vs baseline: 1.3861x; 1.1991x over previous
#include <cuda_runtime.h>
#include <cuda_fp16.h>
#include <cstdint>
#include <cfloat>

#define NHEAD 12
#define NB    4
#define SEQ   2048
#define HDIM  64
#define CDIM  768
#define CDIM3 2304
#define MROWS (NB*SEQ)   // 8192

// fp16 scratch (static device globals: no runtime allocation)
__device__ __align__(16) __half g_q[NB*NHEAD*SEQ*HDIM];  // q pre-scaled by 0.125
__device__ __align__(16) __half g_k[NB*NHEAD*SEQ*HDIM];
__device__ __align__(16) __half g_v[NB*NHEAD*SEQ*HDIM];
__device__ __align__(16) __half g_y[MROWS*CDIM];

__device__ __forceinline__ uint32_t h2pack(float lo, float hi) {
    uint32_t u;
    asm("cvt.rn.f16x2.f32 %0, %1, %2;" : "=r"(u) : "f"(hi), "f"(lo));
    return u;
}

__device__ __forceinline__ uint32_t smem_u32(const void* p) {
    uint32_t a;
    asm("{ .reg .u64 t; cvta.to.shared.u64 t, %1; cvt.u32.u64 %0, t; }"
        : "=r"(a) : "l"(p));
    return a;
}

#define CP16(dst, src) \
    asm volatile("cp.async.cg.shared.global [%0], [%1], 16;" \
                 :: "r"((uint32_t)(dst)), "l"((size_t)(src)) : "memory")
#define CP_COMMIT() asm volatile("cp.async.commit_group;" ::: "memory")
#define CP_WAIT0()  asm volatile("cp.async.wait_group 0;" ::: "memory")

__device__ __forceinline__ void mma16(float* d,
    uint32_t a0, uint32_t a1, uint32_t a2, uint32_t a3,
    uint32_t b0, uint32_t b1) {
    asm volatile(
      "mma.sync.aligned.m16n8k16.row.col.f32.f16.f16.f32 "
      "{%0,%1,%2,%3}, {%4,%5,%6,%7}, {%8,%9}, {%0,%1,%2,%3};\n"
      : "+f"(d[0]), "+f"(d[1]), "+f"(d[2]), "+f"(d[3])
      : "r"(a0), "r"(a1), "r"(a2), "r"(a3), "r"(b0), "r"(b1));
}

#define LDSM_X4(r0,r1,r2,r3,addr) \
    asm volatile("ldmatrix.sync.aligned.m8n8.x4.shared.b16 {%0,%1,%2,%3}, [%4];" \
        : "=r"(r0), "=r"(r1), "=r"(r2), "=r"(r3) : "r"(addr))
#define LDSM_X4T(r0,r1,r2,r3,addr) \
    asm volatile("ldmatrix.sync.aligned.m8n8.x4.trans.shared.b16 {%0,%1,%2,%3}, [%4];" \
        : "=r"(r0), "=r"(r1), "=r"(r2), "=r"(r3) : "r"(addr))

// ---------------------------------------------------------------------------
// Kernel 1: qkv = x @ W_attn + b_attn, fp16 MMA, fp32 accumulate.
// Tile 128(M) x 64(N) x 32(K); 256 thr; warps 4x2 (warp tile 32x32).
// Epilogue writes fp16 q/k/v head-major; q pre-scaled by 0.125.
// ---------------------------------------------------------------------------
__global__ __launch_bounds__(256) void qkv_gemm(
    const float* __restrict__ x, const float* __restrict__ W,
    const float* __restrict__ bias) {
    __shared__ uint32_t As[128*20];   // [m][kw], 16 kwords + 4 pad (bank-clean)
    __shared__ uint32_t Bs[64*20];    // [n][kw], k-packed pairs

    const int tid = threadIdx.x;
    const int wid = tid >> 5, lane = tid & 31;
    const int g = lane >> 2, tg = lane & 3;
    const int wM = wid & 3, wN = wid >> 2;
    const int rowBase = blockIdx.y * 128;
    const int colBase = blockIdx.x * 64;

    const int kwB = tid & 15, n0B = (tid >> 4) * 4;

    float acc[2][4][4];
    #pragma unroll
    for (int i = 0; i < 2; i++)
        #pragma unroll
        for (int j = 0; j < 4; j++)
            #pragma unroll
            for (int e = 0; e < 4; e++) acc[i][j][e] = 0.f;

    for (int kb = 0; kb < CDIM/32; kb++) {
        // A: x rows, k-contiguous; pack fp16 pairs along k
        #pragma unroll
        for (int r = 0; r < 4; r++) {
            int m  = (tid >> 3) + r*32;
            int k4 = (tid & 7) * 4;
            float4 v = *(const float4*)(x + (size_t)(rowBase+m)*CDIM + kb*32 + k4);
            uint2 w;
            w.x = h2pack(v.x, v.y);
            w.y = h2pack(v.z, v.w);
            *(uint2*)&As[m*20 + (tid & 7)*2] = w;
        }
        // B: W[k][n]; pack pairs along k (transpose to [n][kw])
        {
            const float* p0 = W + (size_t)(kb*32 + 2*kwB)*CDIM3 + colBase + n0B;
            float4 r0v = *(const float4*)p0;
            float4 r1v = *(const float4*)(p0 + CDIM3);
            Bs[(n0B+0)*20 + kwB] = h2pack(r0v.x, r1v.x);
            Bs[(n0B+1)*20 + kwB] = h2pack(r0v.y, r1v.y);
            Bs[(n0B+2)*20 + kwB] = h2pack(r0v.z, r1v.z);
            Bs[(n0B+3)*20 + kwB] = h2pack(r0v.w, r1v.w);
        }
        __syncthreads();
        #pragma unroll
        for (int kk = 0; kk < 2; kk++) {
            uint32_t a[2][4], bf[4][2];
            #pragma unroll
            for (int mt = 0; mt < 2; mt++) {
                int r0 = wM*32 + mt*16 + g;
                a[mt][0] = As[ r0    *20 + kk*8 + tg];
                a[mt][1] = As[(r0+8) *20 + kk*8 + tg];
                a[mt][2] = As[ r0    *20 + kk*8 + tg + 4];
                a[mt][3] = As[(r0+8) *20 + kk*8 + tg + 4];
            }
            #pragma unroll
            for (int nt = 0; nt < 4; nt++) {
                int c0 = wN*32 + nt*8 + g;
                bf[nt][0] = Bs[c0*20 + kk*8 + tg];
                bf[nt][1] = Bs[c0*20 + kk*8 + tg + 4];
            }
            #pragma unroll
            for (int mt = 0; mt < 2; mt++)
                #pragma unroll
                for (int nt = 0; nt < 4; nt++)
                    mma16(acc[mt][nt], a[mt][0],a[mt][1],a[mt][2],a[mt][3],
                          bf[nt][0], bf[nt][1]);
        }
        __syncthreads();
    }

    // epilogue: one {q,k,v} x one head per 64-col block; fp16 stores
    const int which = colBase / CDIM;
    const int cj = colBase % CDIM;
    const int h = cj >> 6;
    __half* dst = (which == 0) ? g_q : (which == 1 ? g_k : g_v);
    const float qs = (which == 0) ? 0.125f : 1.0f;

    #pragma unroll
    for (int mt = 0; mt < 2; mt++) {
        int r0g = rowBase + wM*32 + mt*16 + g;
        int r1g = r0g + 8;
        int b0i = r0g >> 11, t0 = r0g & 2047;
        int b1i = r1g >> 11, t1 = r1g & 2047;
        size_t o0 = ((size_t)(b0i*NHEAD + h)*SEQ + t0)*HDIM;
        size_t o1 = ((size_t)(b1i*NHEAD + h)*SEQ + t1)*HDIM;
        #pragma unroll
        for (int nt = 0; nt < 4; nt++) {
            int d0 = wN*32 + nt*8 + tg*2;
            float bb0 = bias[colBase + d0];
            float bb1 = bias[colBase + d0 + 1];
            *(uint32_t*)(dst + o0 + d0) =
                h2pack((acc[mt][nt][0] + bb0)*qs, (acc[mt][nt][1] + bb1)*qs);
            *(uint32_t*)(dst + o1 + d0) =
                h2pack((acc[mt][nt][2] + bb0)*qs, (acc[mt][nt][3] + bb1)*qs);
        }
    }
}

// ---------------------------------------------------------------------------
// Kernel 2: fp16 flash attention. cp.async double-buffered K/V (fp16: 8KB/tile);
// mask seeds fp32 S accumulators before the K/V wait; S C-frag packs directly
// into P A-frag (no smem round trip); V^T via ldmatrix.x4.trans.
// ---------------------------------------------------------------------------
#define KVW 36                         // words per 64-half row (32 + 4 pad)
#define KV_STAGE (64*KVW)
#define VS_BASE  (2*KV_STAGE)
#define FLASH_SMEM ((4*KV_STAGE)*4)    // 36864 B

__global__ __launch_bounds__(256, 2) void flash_attn(const float* __restrict__ mask) {
    extern __shared__ uint32_t sm[];
    uint32_t sb = smem_u32(sm);

    const int tid = threadIdx.x;
    const int wid = tid >> 5, lane = tid & 31;
    const int g = lane >> 2, tg = lane & 3;
    const int qt = (int)(gridDim.x - 1 - blockIdx.x);   // heavy tiles first
    const int h = blockIdx.y >> 2, b = blockIdx.y & 3;
    const int rw = wid * 16;

    const __half* Qg  = g_q + ((size_t)((b*NHEAD + h)*SEQ) + qt*128)*HDIM;
    const __half* Kg0 = g_k + (size_t)((b*NHEAD + h)*SEQ)*HDIM;
    const __half* Vg0 = g_v + (size_t)((b*NHEAD + h)*SEQ)*HDIM;
    const float*  Mb  = mask + ((size_t)h*SEQ + qt*128)*SEQ;

    // cp.async: 64 rows x 128B; 4 thr/row, 2 x 16B chunks each
    const int crow = tid >> 2, cc0 = tid & 3;
    const size_t ksrc0 = __cvta_generic_to_global(Kg0 + (size_t)crow*HDIM);
    const size_t vsrc0 = __cvta_generic_to_global(Vg0 + (size_t)crow*HDIM);
    const uint32_t kdst0 = sb + crow*KVW*4;
    const uint32_t vdst0 = sb + (VS_BASE + crow*KVW)*4;

    #define KV_ISSUE(kt, st) do { \
        size_t ks_ = ksrc0 + (size_t)(kt)*64*HDIM*2; \
        size_t vs_ = vsrc0 + (size_t)(kt)*64*HDIM*2; \
        uint32_t kd_ = kdst0 + (st)*KV_STAGE*4; \
        uint32_t vd_ = vdst0 + (st)*KV_STAGE*4; \
        _Pragma("unroll") \
        for (int j_ = 0; j_ < 2; j_++) { \
            CP16(kd_ + (cc0 + 4*j_)*16, ks_ + (cc0 + 4*j_)*16); \
            CP16(vd_ + (cc0 + 4*j_)*16, vs_ + (cc0 + 4*j_)*16); \
        } \
        CP_COMMIT(); \
    } while (0)

    KV_ISSUE(0, 0);

    // Q fragments: 4 k16-steps, 4 regs each (fp16 pairs straight from global)
    uint32_t qa[4][4];
    {
        const uint32_t* q0 = (const uint32_t*)(Qg + (size_t)(rw+g)*HDIM);
        const uint32_t* q1 = (const uint32_t*)(Qg + (size_t)(rw+8+g)*HDIM);
        #pragma unroll
        for (int kk = 0; kk < 4; kk++) {
            qa[kk][0] = q0[kk*8 + tg];
            qa[kk][1] = q1[kk*8 + tg];
            qa[kk][2] = q0[kk*8 + tg + 4];
            qa[kk][3] = q1[kk*8 + tg + 4];
        }
    }

    // ldmatrix per-lane address components
    const int kRow = (lane & 7) + ((lane >> 4) & 1) * 8;   // n-offset for K tiles
    const int kWof = ((lane >> 3) & 1) * 4;                // b0/b1 word offset
    const int vRow = (lane & 7) + ((lane >> 3) & 1) * 8;   // t-offset for V tiles
    const int vWof = (lane >> 4) * 4;                      // d word offset

    float o[8][4];
    #pragma unroll
    for (int nt = 0; nt < 8; nt++)
        #pragma unroll
        for (int e = 0; e < 4; e++) o[nt][e] = 0.f;
    float m0 = -FLT_MAX, m1 = -FLT_MAX, l0 = 0.f, l1 = 0.f;

    const int ktEnd = 2*qt + 1;
    for (int kt = 0; kt <= ktEnd; kt++) {
        // mask -> S accumulators (issued before K/V wait; latency hidden)
        float s[8][4];
        const float* M0 = Mb + (size_t)(rw+g)*SEQ + kt*64;
        const float* M1 = M0 + (size_t)8*SEQ;
        #pragma unroll
        for (int nt = 0; nt < 8; nt++) {
            float2 u = *(const float2*)(M0 + nt*8 + tg*2);
            float2 w = *(const float2*)(M1 + nt*8 + tg*2);
            s[nt][0] = u.x; s[nt][1] = u.y;
            s[nt][2] = w.x; s[nt][3] = w.y;
        }

        CP_WAIT0();
        __syncthreads();
        if (kt < ktEnd) KV_ISSUE(kt + 1, (kt + 1) & 1);

        const uint32_t kbase = sb + ((kt & 1)*KV_STAGE)*4;
        const uint32_t vbase = sb + (VS_BASE + (kt & 1)*KV_STAGE)*4;

        // S = mask + Q K^T; K b-frags via ldmatrix x4 (2 n-tiles per issue)
        #pragma unroll
        for (int ntp = 0; ntp < 4; ntp++) {
            #pragma unroll
            for (int kk = 0; kk < 4; kk++) {
                uint32_t r0, r1, r2, r3;
                uint32_t ka = kbase + ((ntp*16 + kRow)*KVW + kk*8 + kWof)*4;
                LDSM_X4(r0, r1, r2, r3, ka);
                mma16(s[2*ntp  ], qa[kk][0],qa[kk][1],qa[kk][2],qa[kk][3], r0, r1);
                mma16(s[2*ntp+1], qa[kk][0],qa[kk][1],qa[kk][2],qa[kk][3], r2, r3);
            }
        }

        // online softmax (warp-local rows)
        float rm0 = -FLT_MAX, rm1 = -FLT_MAX;
        #pragma unroll
        for (int nt = 0; nt < 8; nt++) {
            rm0 = fmaxf(rm0, fmaxf(s[nt][0], s[nt][1]));
            rm1 = fmaxf(rm1, fmaxf(s[nt][2], s[nt][3]));
        }
        rm0 = fmaxf(rm0, __shfl_xor_sync(0xffffffffu, rm0, 1));
        rm0 = fmaxf(rm0, __shfl_xor_sync(0xffffffffu, rm0, 2));
        rm1 = fmaxf(rm1, __shfl_xor_sync(0xffffffffu, rm1, 1));
        rm1 = fmaxf(rm1, __shfl_xor_sync(0xffffffffu, rm1, 2));

        float mn0 = fmaxf(m0, rm0), mn1 = fmaxf(m1, rm1);
        float f0 = __expf(m0 - mn0), f1 = __expf(m1 - mn1);
        m0 = mn0; m1 = mn1;

        float rs0 = 0.f, rs1 = 0.f;
        #pragma unroll
        for (int nt = 0; nt < 8; nt++) {
            s[nt][0] = __expf(s[nt][0] - mn0);
            s[nt][1] = __expf(s[nt][1] - mn0);
            s[nt][2] = __expf(s[nt][2] - mn1);
            s[nt][3] = __expf(s[nt][3] - mn1);
            rs0 += s[nt][0] + s[nt][1];
            rs1 += s[nt][2] + s[nt][3];
        }
        l0 = l0*f0 + rs0;
        l1 = l1*f1 + rs1;
        #pragma unroll
        for (int nt = 0; nt < 8; nt++) {
            o[nt][0] *= f0; o[nt][1] *= f0;
            o[nt][2] *= f1; o[nt][3] *= f1;
        }

        // O += P V : P A-frags packed straight from S C-frags (no smem!),
        // V^T b-frags via ldmatrix.x4.trans on raw [t][d] tile
        #pragma unroll
        for (int kk = 0; kk < 4; kk++) {
            uint32_t a0 = h2pack(s[2*kk  ][0], s[2*kk  ][1]);
            uint32_t a1 = h2pack(s[2*kk  ][2], s[2*kk  ][3]);
            uint32_t a2 = h2pack(s[2*kk+1][0], s[2*kk+1][1]);
            uint32_t a3 = h2pack(s[2*kk+1][2], s[2*kk+1][3]);
            #pragma unroll
            for (int ntp = 0; ntp < 4; ntp++) {
                uint32_t r0, r1, r2, r3;
                uint32_t va = vbase + ((kk*16 + vRow)*KVW + ntp*8 + vWof)*4;
                LDSM_X4T(r0, r1, r2, r3, va);
                mma16(o[2*ntp  ], a0, a1, a2, a3, r0, r1);
                mma16(o[2*ntp+1], a0, a1, a2, a3, r2, r3);
            }
        }
    }

    // finalize; write fp16 y (proj's A operand)
    l0 += __shfl_xor_sync(0xffffffffu, l0, 1);
    l0 += __shfl_xor_sync(0xffffffffu, l0, 2);
    l1 += __shfl_xor_sync(0xffffffffu, l1, 1);
    l1 += __shfl_xor_sync(0xffffffffu, l1, 2);
    float inv0 = 1.f / l0, inv1 = 1.f / l1;

    int r0 = qt*128 + rw + g, r1 = r0 + 8;
    __half* y0 = g_y + (size_t)(b*SEQ + r0)*CDIM + h*HDIM;
    __half* y1 = g_y + (size_t)(b*SEQ + r1)*CDIM + h*HDIM;
    #pragma unroll
    for (int nt = 0; nt < 8; nt++) {
        int c = nt*8 + tg*2;
        *(uint32_t*)(y0 + c) = h2pack(o[nt][0]*inv0, o[nt][1]*inv0);
        *(uint32_t*)(y1 + c) = h2pack(o[nt][2]*inv1, o[nt][3]*inv1);
    }
}

// ---------------------------------------------------------------------------
// Kernel 3: out = y(fp16) @ W_proj + b_proj, fp32 out.
// ---------------------------------------------------------------------------
__global__ __launch_bounds__(256) void proj_gemm(
    const float* __restrict__ W, const float* __restrict__ bias,
    float* __restrict__ out) {
    __shared__ uint32_t As[128*20];
    __shared__ uint32_t Bs[64*20];

    const int tid = threadIdx.x;
    const int wid = tid >> 5, lane = tid & 31;
    const int g = lane >> 2, tg = lane & 3;
    const int wM = wid & 3, wN = wid >> 2;
    const int rowBase = blockIdx.y * 128;
    const int colBase = blockIdx.x * 64;

    const int arow = tid >> 1, ahalf = tid & 1;
    const int kwB = tid & 15, n0B = (tid >> 4) * 4;

    float acc[2][4][4];
    #pragma unroll
    for (int i = 0; i < 2; i++)
        #pragma unroll
        for (int j = 0; j < 4; j++)
            #pragma unroll
            for (int e = 0; e < 4; e++) acc[i][j][e] = 0.f;

    for (int kb = 0; kb < CDIM/32; kb++) {
        // A: fp16 y, raw uint4 copies (16 halves per thread)
        {
            const uint4* src = (const uint4*)(g_y + (size_t)(rowBase + arow)*CDIM + kb*32);
            #pragma unroll
            for (int c = 0; c < 2; c++) {
                int idx = ahalf*2 + c;
                *(uint4*)&As[arow*20 + idx*4] = src[idx];
            }
        }
        // B: W_proj fp32 [k][n] -> [n][kw] packed pairs
        {
            const float* p0 = W + (size_t)(kb*32 + 2*kwB)*CDIM + colBase + n0B;
            float4 r0v = *(const float4*)p0;
            float4 r1v = *(const float4*)(p0 + CDIM);
            Bs[(n0B+0)*20 + kwB] = h2pack(r0v.x, r1v.x);
            Bs[(n0B+1)*20 + kwB] = h2pack(r0v.y, r1v.y);
            Bs[(n0B+2)*20 + kwB] = h2pack(r0v.z, r1v.z);
            Bs[(n0B+3)*20 + kwB] = h2pack(r0v.w, r1v.w);
        }
        __syncthreads();
        #pragma unroll
        for (int kk = 0; kk < 2; kk++) {
            uint32_t a[2][4], bf[4][2];
            #pragma unroll
            for (int mt = 0; mt < 2; mt++) {
                int r0 = wM*32 + mt*16 + g;
                a[mt][0] = As[ r0    *20 + kk*8 + tg];
                a[mt][1] = As[(r0+8) *20 + kk*8 + tg];
                a[mt][2] = As[ r0    *20 + kk*8 + tg + 4];
                a[mt][3] = As[(r0+8) *20 + kk*8 + tg + 4];
            }
            #pragma unroll
            for (int nt = 0; nt < 4; nt++) {
                int c0 = wN*32 + nt*8 + g;
                bf[nt][0] = Bs[c0*20 + kk*8 + tg];
                bf[nt][1] = Bs[c0*20 + kk*8 + tg + 4];
            }
            #pragma unroll
            for (int mt = 0; mt < 2; mt++)
                #pragma unroll
                for (int nt = 0; nt < 4; nt++)
                    mma16(acc[mt][nt], a[mt][0],a[mt][1],a[mt][2],a[mt][3],
                          bf[nt][0], bf[nt][1]);
        }
        __syncthreads();
    }

    #pragma unroll
    for (int mt = 0; mt < 2; mt++) {
        int r0g = rowBase + wM*32 + mt*16 + g;
        int r1g = r0g + 8;
        #pragma unroll
        for (int nt = 0; nt < 4; nt++) {
            int j = colBase + wN*32 + nt*8 + tg*2;
            float bb0 = bias[j], bb1 = bias[j+1];
            out[(size_t)r0g*CDIM + j    ] = acc[mt][nt][0] + bb0;
            out[(size_t)r0g*CDIM + j + 1] = acc[mt][nt][1] + bb1;
            out[(size_t)r1g*CDIM + j    ] = acc[mt][nt][2] + bb0;
            out[(size_t)r1g*CDIM + j + 1] = acc[mt][nt][3] + bb1;
        }
    }
}

extern "C" void kernel_launch(void* const* d_in, const int* in_sizes, int n_in,
                              void* d_out, int out_size) {
    const float* x      = (const float*)d_in[0];
    const float* mask   = (const float*)d_in[1];
    const float* W_attn = (const float*)d_in[2];
    const float* b_attn = (const float*)d_in[3];
    const float* W_proj = (const float*)d_in[4];
    const float* b_proj = (const float*)d_in[5];
    float* out = (float*)d_out;

    cudaFuncSetAttribute((const void*)flash_attn,
                         cudaFuncAttributeMaxDynamicSharedMemorySize, FLASH_SMEM);

    dim3 g1(CDIM3/64, MROWS/128);      // 36 x 64
    qkv_gemm<<<g1, 256>>>(x, W_attn, b_attn);

    dim3 g2(SEQ/128, NHEAD*NB);        // 16 x 48 (h-major: mask L2 reuse over b)
    flash_attn<<<g2, 256, FLASH_SMEM>>>(mask);

    dim3 g3(CDIM/64, MROWS/128);       // 12 x 64
    proj_gemm<<<g3, 256>>>(W_proj, b_proj, out);
}

// round 7
// speedup vs baseline: 2.3330x; 1.6832x over previous
#include <cuda_runtime.h>
#include <cuda_fp16.h>
#include <cstdint>
#include <cfloat>

#define NHEAD 12
#define NB    4
#define SEQ   2048
#define HDIM  64
#define CDIM  768
#define CDIM3 2304
#define MROWS (NB*SEQ)   // 8192

// fp16 scratch (static device globals: no runtime allocation)
__device__ __align__(16) __half g_q[NB*NHEAD*SEQ*HDIM];  // q pre-scaled by 0.125
__device__ __align__(16) __half g_k[NB*NHEAD*SEQ*HDIM];
__device__ __align__(16) __half g_v[NB*NHEAD*SEQ*HDIM];
__device__ __align__(16) __half g_y[MROWS*CDIM];
__device__ __align__(16) __half g_xh[MROWS*CDIM];        // x fp16
__device__ __align__(16) __half g_wah[CDIM3*CDIM];       // W_attn^T fp16 [n][k]
__device__ __align__(16) __half g_wph[CDIM*CDIM];        // W_proj^T fp16 [n][k]

__device__ __forceinline__ uint32_t h2pack(float lo, float hi) {
    uint32_t u;
    asm("cvt.rn.f16x2.f32 %0, %1, %2;" : "=r"(u) : "f"(hi), "f"(lo));
    return u;
}

__device__ __forceinline__ uint32_t smem_u32(const void* p) {
    uint32_t a;
    asm("{ .reg .u64 t; cvta.to.shared.u64 t, %1; cvt.u32.u64 %0, t; }"
        : "=r"(a) : "l"(p));
    return a;
}

#define CP16(dst, src) \
    asm volatile("cp.async.cg.shared.global [%0], [%1], 16;" \
                 :: "r"((uint32_t)(dst)), "l"((size_t)(src)) : "memory")
#define CP_COMMIT() asm volatile("cp.async.commit_group;" ::: "memory")
#define CP_WAIT0()  asm volatile("cp.async.wait_group 0;" ::: "memory")

__device__ __forceinline__ void mma16(float* d,
    uint32_t a0, uint32_t a1, uint32_t a2, uint32_t a3,
    uint32_t b0, uint32_t b1) {
    asm volatile(
      "mma.sync.aligned.m16n8k16.row.col.f32.f16.f16.f32 "
      "{%0,%1,%2,%3}, {%4,%5,%6,%7}, {%8,%9}, {%0,%1,%2,%3};\n"
      : "+f"(d[0]), "+f"(d[1]), "+f"(d[2]), "+f"(d[3])
      : "r"(a0), "r"(a1), "r"(a2), "r"(a3), "r"(b0), "r"(b1));
}

#define LDSM_X4(r0,r1,r2,r3,addr) \
    asm volatile("ldmatrix.sync.aligned.m8n8.x4.shared.b16 {%0,%1,%2,%3}, [%4];" \
        : "=r"(r0), "=r"(r1), "=r"(r2), "=r"(r3) : "r"(addr))
#define LDSM_X4T(r0,r1,r2,r3,addr) \
    asm volatile("ldmatrix.sync.aligned.m8n8.x4.trans.shared.b16 {%0,%1,%2,%3}, [%4];" \
        : "=r"(r0), "=r"(r1), "=r"(r2), "=r"(r3) : "r"(addr))

// ===================== prep kernels =========================================
__global__ __launch_bounds__(256) void f2h(const float* __restrict__ src,
                                           __half* __restrict__ dst) {
    size_t i = ((size_t)blockIdx.x * 256 + threadIdx.x) * 4;
    float4 v = *(const float4*)(src + i);
    uint2 o;
    o.x = h2pack(v.x, v.y);
    o.y = h2pack(v.z, v.w);
    *(uint2*)(dst + i) = o;
}

// src [K][N] fp32 row-major -> dst [N][K] fp16 row-major
__global__ __launch_bounds__(256) void transpose_h(
    const float* __restrict__ src, __half* __restrict__ dst, int K, int N) {
    __shared__ float t[32][33];
    int nb = blockIdx.x * 32, kb = blockIdx.y * 32;
    int tx = threadIdx.x & 31, ty = threadIdx.x >> 5;
    #pragma unroll
    for (int r = 0; r < 4; r++)
        t[ty + r*8][tx] = src[(size_t)(kb + ty + r*8) * N + nb + tx];
    __syncthreads();
    #pragma unroll
    for (int r = 0; r < 4; r++)
        dst[(size_t)(nb + ty + r*8) * K + kb + tx] = __float2half_rn(t[tx][ty + r*8]);
}

// ===================== fp16 GEMM core (128x128x64, ldmatrix) ================
#define GP 36   // smem pitch in words (64 halves + 4 pad words)

// shared fragment-address lane components
#define GEMM_LANE_SETUP() \
    const int tid = threadIdx.x; \
    const int wid = tid >> 5, lane = tid & 31; \
    const int g = lane >> 2, tg = lane & 3; \
    const int wM = wid & 3, wN = wid >> 2; \
    const int aRow = (lane & 7) + ((lane >> 3) & 1) * 8, aWof = (lane >> 4) * 4; \
    const int bRow = (lane & 7) + ((lane >> 4) & 1) * 8, bWof = ((lane >> 3) & 1) * 4; \
    const int lrow = tid >> 3, lseg = tid & 7;

#define GEMM_MAINLOOP(Asrc, Bsrc, Apitch, Bpitch) \
    float acc[2][8][4]; \
    _Pragma("unroll") \
    for (int i = 0; i < 2; i++) \
        _Pragma("unroll") \
        for (int j = 0; j < 8; j++) \
            _Pragma("unroll") \
            for (int e = 0; e < 4; e++) acc[i][j][e] = 0.f; \
    for (int kb = 0; kb < CDIM/64; kb++) { \
        _Pragma("unroll") \
        for (int j = 0; j < 4; j++) { \
            int r = lrow + j*32; \
            *(uint4*)&Ah[r*GP + lseg*4] = \
                *(const uint4*)(Asrc + (size_t)(rowBase + r)*(Apitch) + kb*64 + lseg*8); \
            *(uint4*)&Bh[r*GP + lseg*4] = \
                *(const uint4*)(Bsrc + (size_t)(colBase + r)*(Bpitch) + kb*64 + lseg*8); \
        } \
        __syncthreads(); \
        _Pragma("unroll") \
        for (int kk = 0; kk < 4; kk++) { \
            uint32_t a0[4], a1[4]; \
            LDSM_X4(a0[0],a0[1],a0[2],a0[3], sbA + ((wM*32      + aRow)*GP + kk*8 + aWof)*4); \
            LDSM_X4(a1[0],a1[1],a1[2],a1[3], sbA + ((wM*32 + 16 + aRow)*GP + kk*8 + aWof)*4); \
            _Pragma("unroll") \
            for (int ntp = 0; ntp < 4; ntp++) { \
                uint32_t b0, b1, b2, b3; \
                LDSM_X4(b0, b1, b2, b3, \
                        sbB + ((wN*64 + ntp*16 + bRow)*GP + kk*8 + bWof)*4); \
                mma16(acc[0][2*ntp  ], a0[0],a0[1],a0[2],a0[3], b0, b1); \
                mma16(acc[0][2*ntp+1], a0[0],a0[1],a0[2],a0[3], b2, b3); \
                mma16(acc[1][2*ntp  ], a1[0],a1[1],a1[2],a1[3], b0, b1); \
                mma16(acc[1][2*ntp+1], a1[0],a1[1],a1[2],a1[3], b2, b3); \
            } \
        } \
        __syncthreads(); \
    }

// ---------------------------------------------------------------------------
// Kernel 1: qkv = xh @ wah^T + b_attn -> fp16 head-major q/k/v (q * 0.125)
// ---------------------------------------------------------------------------
__global__ __launch_bounds__(256) void qkv_gemm(const float* __restrict__ bias) {
    __shared__ uint32_t Ah[128*GP];
    __shared__ uint32_t Bh[128*GP];
    GEMM_LANE_SETUP();
    const int rowBase = blockIdx.y * 128;
    const int colBase = blockIdx.x * 128;
    const uint32_t sbA = smem_u32(Ah), sbB = smem_u32(Bh);

    GEMM_MAINLOOP(g_xh, g_wah, CDIM, CDIM);

    const int which = colBase / CDIM;           // 128 | 768 blocks: exact
    const int cjBase = colBase % CDIM;
    __half* dst = (which == 0) ? g_q : (which == 1 ? g_k : g_v);
    const float qs = (which == 0) ? 0.125f : 1.0f;

    #pragma unroll
    for (int mt = 0; mt < 2; mt++) {
        int r0g = rowBase + wM*32 + mt*16 + g;
        int r1g = r0g + 8;
        int b0i = r0g >> 11, t0 = r0g & 2047;
        int b1i = r1g >> 11, t1 = r1g & 2047;
        #pragma unroll
        for (int nt = 0; nt < 8; nt++) {
            int cj = cjBase + wN*64 + nt*8 + tg*2;
            int h = cj >> 6, d = cj & 63;
            int n = colBase + wN*64 + nt*8 + tg*2;
            float bb0 = bias[n], bb1 = bias[n+1];
            size_t o0 = ((size_t)(b0i*NHEAD + h)*SEQ + t0)*HDIM + d;
            size_t o1 = ((size_t)(b1i*NHEAD + h)*SEQ + t1)*HDIM + d;
            *(uint32_t*)(dst + o0) =
                h2pack((acc[mt][nt][0] + bb0)*qs, (acc[mt][nt][1] + bb1)*qs);
            *(uint32_t*)(dst + o1) =
                h2pack((acc[mt][nt][2] + bb0)*qs, (acc[mt][nt][3] + bb1)*qs);
        }
    }
}

// ---------------------------------------------------------------------------
// Kernel 3: out = y(fp16) @ wph^T + b_proj, fp32 out
// ---------------------------------------------------------------------------
__global__ __launch_bounds__(256) void proj_gemm(const float* __restrict__ bias,
                                                 float* __restrict__ out) {
    __shared__ uint32_t Ah[128*GP];
    __shared__ uint32_t Bh[128*GP];
    GEMM_LANE_SETUP();
    const int rowBase = blockIdx.y * 128;
    const int colBase = blockIdx.x * 128;
    const uint32_t sbA = smem_u32(Ah), sbB = smem_u32(Bh);

    GEMM_MAINLOOP(g_y, g_wph, CDIM, CDIM);

    #pragma unroll
    for (int mt = 0; mt < 2; mt++) {
        int r0g = rowBase + wM*32 + mt*16 + g;
        int r1g = r0g + 8;
        #pragma unroll
        for (int nt = 0; nt < 8; nt++) {
            int n = colBase + wN*64 + nt*8 + tg*2;
            float bb0 = bias[n], bb1 = bias[n+1];
            float2 u0 = {acc[mt][nt][0] + bb0, acc[mt][nt][1] + bb1};
            float2 u1 = {acc[mt][nt][2] + bb0, acc[mt][nt][3] + bb1};
            *(float2*)(out + (size_t)r0g*CDIM + n) = u0;
            *(float2*)(out + (size_t)r1g*CDIM + n) = u1;
        }
    }
}

// ---------------------------------------------------------------------------
// Kernel 2: fp16 flash attention (unchanged from R6 — proven)
// ---------------------------------------------------------------------------
#define KVW 36
#define KV_STAGE (64*KVW)
#define VS_BASE  (2*KV_STAGE)
#define FLASH_SMEM ((4*KV_STAGE)*4)    // 36864 B

__global__ __launch_bounds__(256, 2) void flash_attn(const float* __restrict__ mask) {
    extern __shared__ uint32_t sm[];
    uint32_t sb = smem_u32(sm);

    const int tid = threadIdx.x;
    const int wid = tid >> 5, lane = tid & 31;
    const int g = lane >> 2, tg = lane & 3;
    const int qt = (int)(gridDim.x - 1 - blockIdx.x);
    const int h = blockIdx.y >> 2, b = blockIdx.y & 3;
    const int rw = wid * 16;

    const __half* Qg  = g_q + ((size_t)((b*NHEAD + h)*SEQ) + qt*128)*HDIM;
    const __half* Kg0 = g_k + (size_t)((b*NHEAD + h)*SEQ)*HDIM;
    const __half* Vg0 = g_v + (size_t)((b*NHEAD + h)*SEQ)*HDIM;
    const float*  Mb  = mask + ((size_t)h*SEQ + qt*128)*SEQ;

    const int crow = tid >> 2, cc0 = tid & 3;
    const size_t ksrc0 = __cvta_generic_to_global(Kg0 + (size_t)crow*HDIM);
    const size_t vsrc0 = __cvta_generic_to_global(Vg0 + (size_t)crow*HDIM);
    const uint32_t kdst0 = sb + crow*KVW*4;
    const uint32_t vdst0 = sb + (VS_BASE + crow*KVW)*4;

    #define KV_ISSUE(kt, st) do { \
        size_t ks_ = ksrc0 + (size_t)(kt)*64*HDIM*2; \
        size_t vs_ = vsrc0 + (size_t)(kt)*64*HDIM*2; \
        uint32_t kd_ = kdst0 + (st)*KV_STAGE*4; \
        uint32_t vd_ = vdst0 + (st)*KV_STAGE*4; \
        _Pragma("unroll") \
        for (int j_ = 0; j_ < 2; j_++) { \
            CP16(kd_ + (cc0 + 4*j_)*16, ks_ + (cc0 + 4*j_)*16); \
            CP16(vd_ + (cc0 + 4*j_)*16, vs_ + (cc0 + 4*j_)*16); \
        } \
        CP_COMMIT(); \
    } while (0)

    KV_ISSUE(0, 0);

    uint32_t qa[4][4];
    {
        const uint32_t* q0 = (const uint32_t*)(Qg + (size_t)(rw+g)*HDIM);
        const uint32_t* q1 = (const uint32_t*)(Qg + (size_t)(rw+8+g)*HDIM);
        #pragma unroll
        for (int kk = 0; kk < 4; kk++) {
            qa[kk][0] = q0[kk*8 + tg];
            qa[kk][1] = q1[kk*8 + tg];
            qa[kk][2] = q0[kk*8 + tg + 4];
            qa[kk][3] = q1[kk*8 + tg + 4];
        }
    }

    const int kRow = (lane & 7) + ((lane >> 4) & 1) * 8;
    const int kWof = ((lane >> 3) & 1) * 4;
    const int vRow = (lane & 7) + ((lane >> 3) & 1) * 8;
    const int vWof = (lane >> 4) * 4;

    float o[8][4];
    #pragma unroll
    for (int nt = 0; nt < 8; nt++)
        #pragma unroll
        for (int e = 0; e < 4; e++) o[nt][e] = 0.f;
    float m0 = -FLT_MAX, m1 = -FLT_MAX, l0 = 0.f, l1 = 0.f;

    const int ktEnd = 2*qt + 1;
    for (int kt = 0; kt <= ktEnd; kt++) {
        float s[8][4];
        const float* M0 = Mb + (size_t)(rw+g)*SEQ + kt*64;
        const float* M1 = M0 + (size_t)8*SEQ;
        #pragma unroll
        for (int nt = 0; nt < 8; nt++) {
            float2 u = *(const float2*)(M0 + nt*8 + tg*2);
            float2 w = *(const float2*)(M1 + nt*8 + tg*2);
            s[nt][0] = u.x; s[nt][1] = u.y;
            s[nt][2] = w.x; s[nt][3] = w.y;
        }

        CP_WAIT0();
        __syncthreads();
        if (kt < ktEnd) KV_ISSUE(kt + 1, (kt + 1) & 1);

        const uint32_t kbase = sb + ((kt & 1)*KV_STAGE)*4;
        const uint32_t vbase = sb + (VS_BASE + (kt & 1)*KV_STAGE)*4;

        #pragma unroll
        for (int ntp = 0; ntp < 4; ntp++) {
            #pragma unroll
            for (int kk = 0; kk < 4; kk++) {
                uint32_t r0, r1, r2, r3;
                uint32_t ka = kbase + ((ntp*16 + kRow)*KVW + kk*8 + kWof)*4;
                LDSM_X4(r0, r1, r2, r3, ka);
                mma16(s[2*ntp  ], qa[kk][0],qa[kk][1],qa[kk][2],qa[kk][3], r0, r1);
                mma16(s[2*ntp+1], qa[kk][0],qa[kk][1],qa[kk][2],qa[kk][3], r2, r3);
            }
        }

        float rm0 = -FLT_MAX, rm1 = -FLT_MAX;
        #pragma unroll
        for (int nt = 0; nt < 8; nt++) {
            rm0 = fmaxf(rm0, fmaxf(s[nt][0], s[nt][1]));
            rm1 = fmaxf(rm1, fmaxf(s[nt][2], s[nt][3]));
        }
        rm0 = fmaxf(rm0, __shfl_xor_sync(0xffffffffu, rm0, 1));
        rm0 = fmaxf(rm0, __shfl_xor_sync(0xffffffffu, rm0, 2));
        rm1 = fmaxf(rm1, __shfl_xor_sync(0xffffffffu, rm1, 1));
        rm1 = fmaxf(rm1, __shfl_xor_sync(0xffffffffu, rm1, 2));

        float mn0 = fmaxf(m0, rm0), mn1 = fmaxf(m1, rm1);
        float f0 = __expf(m0 - mn0), f1 = __expf(m1 - mn1);
        m0 = mn0; m1 = mn1;

        float rs0 = 0.f, rs1 = 0.f;
        #pragma unroll
        for (int nt = 0; nt < 8; nt++) {
            s[nt][0] = __expf(s[nt][0] - mn0);
            s[nt][1] = __expf(s[nt][1] - mn0);
            s[nt][2] = __expf(s[nt][2] - mn1);
            s[nt][3] = __expf(s[nt][3] - mn1);
            rs0 += s[nt][0] + s[nt][1];
            rs1 += s[nt][2] + s[nt][3];
        }
        l0 = l0*f0 + rs0;
        l1 = l1*f1 + rs1;
        #pragma unroll
        for (int nt = 0; nt < 8; nt++) {
            o[nt][0] *= f0; o[nt][1] *= f0;
            o[nt][2] *= f1; o[nt][3] *= f1;
        }

        #pragma unroll
        for (int kk = 0; kk < 4; kk++) {
            uint32_t a0 = h2pack(s[2*kk  ][0], s[2*kk  ][1]);
            uint32_t a1 = h2pack(s[2*kk  ][2], s[2*kk  ][3]);
            uint32_t a2 = h2pack(s[2*kk+1][0], s[2*kk+1][1]);
            uint32_t a3 = h2pack(s[2*kk+1][2], s[2*kk+1][3]);
            #pragma unroll
            for (int ntp = 0; ntp < 4; ntp++) {
                uint32_t r0, r1, r2, r3;
                uint32_t va = vbase + ((kk*16 + vRow)*KVW + ntp*8 + vWof)*4;
                LDSM_X4T(r0, r1, r2, r3, va);
                mma16(o[2*ntp  ], a0, a1, a2, a3, r0, r1);
                mma16(o[2*ntp+1], a0, a1, a2, a3, r2, r3);
            }
        }
    }

    l0 += __shfl_xor_sync(0xffffffffu, l0, 1);
    l0 += __shfl_xor_sync(0xffffffffu, l0, 2);
    l1 += __shfl_xor_sync(0xffffffffu, l1, 1);
    l1 += __shfl_xor_sync(0xffffffffu, l1, 2);
    float inv0 = 1.f / l0, inv1 = 1.f / l1;

    int r0 = qt*128 + rw + g, r1 = r0 + 8;
    __half* y0 = g_y + (size_t)(b*SEQ + r0)*CDIM + h*HDIM;
    __half* y1 = g_y + (size_t)(b*SEQ + r1)*CDIM + h*HDIM;
    #pragma unroll
    for (int nt = 0; nt < 8; nt++) {
        int c = nt*8 + tg*2;
        *(uint32_t*)(y0 + c) = h2pack(o[nt][0]*inv0, o[nt][1]*inv0);
        *(uint32_t*)(y1 + c) = h2pack(o[nt][2]*inv1, o[nt][3]*inv1);
    }
}

// ===================== host =================================================
extern "C" void kernel_launch(void* const* d_in, const int* in_sizes, int n_in,
                              void* d_out, int out_size) {
    const float* x      = (const float*)d_in[0];
    const float* mask   = (const float*)d_in[1];
    const float* W_attn = (const float*)d_in[2];
    const float* b_attn = (const float*)d_in[3];
    const float* W_proj = (const float*)d_in[4];
    const float* b_proj = (const float*)d_in[5];
    float* out = (float*)d_out;

    void *p_xh, *p_wah, *p_wph;
    cudaGetSymbolAddress(&p_xh,  g_xh);
    cudaGetSymbolAddress(&p_wah, g_wah);
    cudaGetSymbolAddress(&p_wph, g_wph);

    cudaFuncSetAttribute((const void*)flash_attn,
                         cudaFuncAttributeMaxDynamicSharedMemorySize, FLASH_SMEM);

    // prep: fp16 conversions (x row-major; weights transposed to [n][k])
    f2h<<<(MROWS*CDIM/4)/256, 256>>>(x, (__half*)p_xh);
    transpose_h<<<dim3(CDIM3/32, CDIM/32), 256>>>(W_attn, (__half*)p_wah, CDIM, CDIM3);
    transpose_h<<<dim3(CDIM/32, CDIM/32), 256>>>(W_proj, (__half*)p_wph, CDIM, CDIM);

    dim3 g1(CDIM3/128, MROWS/128);     // 18 x 64
    qkv_gemm<<<g1, 256>>>(b_attn);

    dim3 g2(SEQ/128, NHEAD*NB);        // 16 x 48 (h-major: mask L2 reuse over b)
    flash_attn<<<g2, 256, FLASH_SMEM>>>(mask);

    dim3 g3(CDIM/128, MROWS/128);      // 6 x 64
    proj_gemm<<<g3, 256>>>(b_proj, out);
}

// round 8
// speedup vs baseline: 2.6202x; 1.1231x over previous
#include <cuda_runtime.h>
#include <cuda_fp16.h>
#include <cstdint>
#include <cfloat>

#define NHEAD 12
#define NB    4
#define SEQ   2048
#define HDIM  64
#define CDIM  768
#define CDIM3 2304
#define MROWS (NB*SEQ)   // 8192

// fp16 scratch (static device globals: no runtime allocation)
__device__ __align__(16) __half g_q[NB*NHEAD*SEQ*HDIM];  // q pre-scaled by 0.125
__device__ __align__(16) __half g_k[NB*NHEAD*SEQ*HDIM];
__device__ __align__(16) __half g_v[NB*NHEAD*SEQ*HDIM];
__device__ __align__(16) __half g_y[MROWS*CDIM];
__device__ __align__(16) __half g_xh[MROWS*CDIM];        // x fp16
__device__ __align__(16) __half g_wah[CDIM3*CDIM];       // W_attn^T fp16 [n][k]
__device__ __align__(16) __half g_wph[CDIM*CDIM];        // W_proj^T fp16 [n][k]

__device__ __forceinline__ uint32_t h2pack(float lo, float hi) {
    uint32_t u;
    asm("cvt.rn.f16x2.f32 %0, %1, %2;" : "=r"(u) : "f"(hi), "f"(lo));
    return u;
}

__device__ __forceinline__ uint32_t smem_u32(const void* p) {
    uint32_t a;
    asm("{ .reg .u64 t; cvta.to.shared.u64 t, %1; cvt.u32.u64 %0, t; }"
        : "=r"(a) : "l"(p));
    return a;
}

#define CP16(dst, src) \
    asm volatile("cp.async.cg.shared.global [%0], [%1], 16;" \
                 :: "r"((uint32_t)(dst)), "l"((size_t)(src)) : "memory")
#define CP16A(dst, src) \
    asm volatile("cp.async.ca.shared.global [%0], [%1], 16;" \
                 :: "r"((uint32_t)(dst)), "l"((size_t)(src)) : "memory")
#define CP_COMMIT() asm volatile("cp.async.commit_group;" ::: "memory")
#define CP_WAIT0()  asm volatile("cp.async.wait_group 0;" ::: "memory")

__device__ __forceinline__ void mma16(float* d,
    uint32_t a0, uint32_t a1, uint32_t a2, uint32_t a3,
    uint32_t b0, uint32_t b1) {
    asm volatile(
      "mma.sync.aligned.m16n8k16.row.col.f32.f16.f16.f32 "
      "{%0,%1,%2,%3}, {%4,%5,%6,%7}, {%8,%9}, {%0,%1,%2,%3};\n"
      : "+f"(d[0]), "+f"(d[1]), "+f"(d[2]), "+f"(d[3])
      : "r"(a0), "r"(a1), "r"(a2), "r"(a3), "r"(b0), "r"(b1));
}

#define LDSM_X4(r0,r1,r2,r3,addr) \
    asm volatile("ldmatrix.sync.aligned.m8n8.x4.shared.b16 {%0,%1,%2,%3}, [%4];" \
        : "=r"(r0), "=r"(r1), "=r"(r2), "=r"(r3) : "r"(addr))
#define LDSM_X4T(r0,r1,r2,r3,addr) \
    asm volatile("ldmatrix.sync.aligned.m8n8.x4.trans.shared.b16 {%0,%1,%2,%3}, [%4];" \
        : "=r"(r0), "=r"(r1), "=r"(r2), "=r"(r3) : "r"(addr))

// ===================== prep kernels =========================================
__global__ __launch_bounds__(256) void f2h(const float* __restrict__ src,
                                           __half* __restrict__ dst) {
    size_t i = ((size_t)blockIdx.x * 256 + threadIdx.x) * 4;
    float4 v = *(const float4*)(src + i);
    uint2 o;
    o.x = h2pack(v.x, v.y);
    o.y = h2pack(v.z, v.w);
    *(uint2*)(dst + i) = o;
}

// src [K][N] fp32 row-major -> dst [N][K] fp16 row-major
__global__ __launch_bounds__(256) void transpose_h(
    const float* __restrict__ src, __half* __restrict__ dst, int K, int N) {
    __shared__ float t[32][33];
    int nb = blockIdx.x * 32, kb = blockIdx.y * 32;
    int tx = threadIdx.x & 31, ty = threadIdx.x >> 5;
    #pragma unroll
    for (int r = 0; r < 4; r++)
        t[ty + r*8][tx] = src[(size_t)(kb + ty + r*8) * N + nb + tx];
    __syncthreads();
    #pragma unroll
    for (int r = 0; r < 4; r++)
        dst[(size_t)(nb + ty + r*8) * K + kb + tx] = __float2half_rn(t[tx][ty + r*8]);
}

// ===================== fp16 GEMM core (128x128x64, cp.async 2-stage) ========
#define GP 36                 // smem pitch in words (64 halves + 4 pad words)
#define ABS (128*GP)          // words per tile array
#define G_SMEM (2*2*ABS*4)    // 73728 B (2 stages x {A,B})

#define GEMM_LANE_SETUP() \
    const int tid = threadIdx.x; \
    const int wid = tid >> 5, lane = tid & 31; \
    const int g = lane >> 2, tg = lane & 3; \
    const int wM = wid & 3, wN = wid >> 2; \
    const int aRow = (lane & 7) + ((lane >> 3) & 1) * 8, aWof = (lane >> 4) * 4; \
    const int bRow = (lane & 7) + ((lane >> 4) & 1) * 8, bWof = ((lane >> 3) & 1) * 4; \
    const int lrow = tid >> 3, lseg = tid & 7;

// issue one 64-K stage: A rows from Asrc, B rows from Bsrc (both pitch CDIM)
#define GEMM_ISSUE(kb, st) do { \
    size_t ko_ = (size_t)(kb)*64*2; \
    uint32_t ad_ = sb + ((st)*2*ABS)*4; \
    uint32_t bd_ = sb + ((st)*2*ABS + ABS)*4; \
    _Pragma("unroll") \
    for (int j_ = 0; j_ < 4; j_++) { \
        CP16A(ad_ + (((lrow + j_*32)*GP + lseg*4))*4, aG + (size_t)(j_*32)*CDIM*2 + ko_); \
        CP16A(bd_ + (((lrow + j_*32)*GP + lseg*4))*4, bG + (size_t)(j_*32)*CDIM*2 + ko_); \
    } \
    CP_COMMIT(); \
} while (0)

#define GEMM_MAINLOOP() \
    float acc[2][8][4]; \
    _Pragma("unroll") \
    for (int i = 0; i < 2; i++) \
        _Pragma("unroll") \
        for (int j = 0; j < 8; j++) \
            _Pragma("unroll") \
            for (int e = 0; e < 4; e++) acc[i][j][e] = 0.f; \
    GEMM_ISSUE(0, 0); \
    for (int kb = 0; kb < CDIM/64; kb++) { \
        CP_WAIT0(); \
        __syncthreads(); \
        if (kb + 1 < CDIM/64) GEMM_ISSUE(kb + 1, (kb + 1) & 1); \
        const uint32_t sbA = sb + ((kb & 1)*2*ABS)*4; \
        const uint32_t sbB = sbA + ABS*4; \
        _Pragma("unroll") \
        for (int kk = 0; kk < 4; kk++) { \
            uint32_t a0[4], a1[4]; \
            LDSM_X4(a0[0],a0[1],a0[2],a0[3], sbA + ((wM*32      + aRow)*GP + kk*8 + aWof)*4); \
            LDSM_X4(a1[0],a1[1],a1[2],a1[3], sbA + ((wM*32 + 16 + aRow)*GP + kk*8 + aWof)*4); \
            _Pragma("unroll") \
            for (int ntp = 0; ntp < 4; ntp++) { \
                uint32_t b0, b1, b2, b3; \
                LDSM_X4(b0, b1, b2, b3, \
                        sbB + ((wN*64 + ntp*16 + bRow)*GP + kk*8 + bWof)*4); \
                mma16(acc[0][2*ntp  ], a0[0],a0[1],a0[2],a0[3], b0, b1); \
                mma16(acc[0][2*ntp+1], a0[0],a0[1],a0[2],a0[3], b2, b3); \
                mma16(acc[1][2*ntp  ], a1[0],a1[1],a1[2],a1[3], b0, b1); \
                mma16(acc[1][2*ntp+1], a1[0],a1[1],a1[2],a1[3], b2, b3); \
            } \
        } \
        __syncthreads(); \
    }

// ---------------------------------------------------------------------------
// Kernel 1: qkv = xh @ wah^T + b_attn -> fp16 head-major q/k/v (q * 0.125)
// ---------------------------------------------------------------------------
__global__ __launch_bounds__(256) void qkv_gemm(const float* __restrict__ bias) {
    extern __shared__ uint32_t smw[];
    uint32_t sb = smem_u32(smw);
    GEMM_LANE_SETUP();
    const int rowBase = blockIdx.y * 128;
    const int colBase = blockIdx.x * 128;
    const size_t aG = __cvta_generic_to_global(g_xh  + (size_t)(rowBase + lrow)*CDIM + lseg*8);
    const size_t bG = __cvta_generic_to_global(g_wah + (size_t)(colBase + lrow)*CDIM + lseg*8);

    GEMM_MAINLOOP();

    const int which = colBase / CDIM;
    const int cjBase = colBase % CDIM;
    __half* dst = (which == 0) ? g_q : (which == 1 ? g_k : g_v);
    const float qs = (which == 0) ? 0.125f : 1.0f;

    #pragma unroll
    for (int mt = 0; mt < 2; mt++) {
        int r0g = rowBase + wM*32 + mt*16 + g;
        int r1g = r0g + 8;
        int b0i = r0g >> 11, t0 = r0g & 2047;
        int b1i = r1g >> 11, t1 = r1g & 2047;
        #pragma unroll
        for (int nt = 0; nt < 8; nt++) {
            int cj = cjBase + wN*64 + nt*8 + tg*2;
            int h = cj >> 6, d = cj & 63;
            int n = colBase + wN*64 + nt*8 + tg*2;
            float bb0 = bias[n], bb1 = bias[n+1];
            size_t o0 = ((size_t)(b0i*NHEAD + h)*SEQ + t0)*HDIM + d;
            size_t o1 = ((size_t)(b1i*NHEAD + h)*SEQ + t1)*HDIM + d;
            *(uint32_t*)(dst + o0) =
                h2pack((acc[mt][nt][0] + bb0)*qs, (acc[mt][nt][1] + bb1)*qs);
            *(uint32_t*)(dst + o1) =
                h2pack((acc[mt][nt][2] + bb0)*qs, (acc[mt][nt][3] + bb1)*qs);
        }
    }
}

// ---------------------------------------------------------------------------
// Kernel 3: out = y(fp16) @ wph^T + b_proj, fp32 out
// ---------------------------------------------------------------------------
__global__ __launch_bounds__(256) void proj_gemm(const float* __restrict__ bias,
                                                 float* __restrict__ out) {
    extern __shared__ uint32_t smw[];
    uint32_t sb = smem_u32(smw);
    GEMM_LANE_SETUP();
    const int rowBase = blockIdx.y * 128;
    const int colBase = blockIdx.x * 128;
    const size_t aG = __cvta_generic_to_global(g_y   + (size_t)(rowBase + lrow)*CDIM + lseg*8);
    const size_t bG = __cvta_generic_to_global(g_wph + (size_t)(colBase + lrow)*CDIM + lseg*8);

    GEMM_MAINLOOP();

    #pragma unroll
    for (int mt = 0; mt < 2; mt++) {
        int r0g = rowBase + wM*32 + mt*16 + g;
        int r1g = r0g + 8;
        #pragma unroll
        for (int nt = 0; nt < 8; nt++) {
            int n = colBase + wN*64 + nt*8 + tg*2;
            float bb0 = bias[n], bb1 = bias[n+1];
            float2 u0 = {acc[mt][nt][0] + bb0, acc[mt][nt][1] + bb1};
            float2 u1 = {acc[mt][nt][2] + bb0, acc[mt][nt][3] + bb1};
            *(float2*)(out + (size_t)r0g*CDIM + n) = u0;
            *(float2*)(out + (size_t)r1g*CDIM + n) = u1;
        }
    }
}

// ---------------------------------------------------------------------------
// Kernel 2: fp16 flash attention with K/V row permutation so each thread's
// S fragment covers 4 CONSECUTIVE logical columns -> mask loads are LDG.128.
// Permutation (within each 16-row group): phys p <- logical l where
//   p<8:  l = 4*(p>>1) + (p&1);   p>=8: l = 4*((p-8)>>1) + 2 + (p&1)
// Softmax reductions and P@V are permutation-invariant (V rows permuted same).
// ---------------------------------------------------------------------------
#define KVW 36
#define KV_STAGE (64*KVW)
#define VS_BASE  (2*KV_STAGE)
#define FLASH_SMEM ((4*KV_STAGE)*4)    // 36864 B

__global__ __launch_bounds__(256, 2) void flash_attn(const float* __restrict__ mask) {
    extern __shared__ uint32_t sm[];
    uint32_t sb = smem_u32(sm);

    const int tid = threadIdx.x;
    const int wid = tid >> 5, lane = tid & 31;
    const int g = lane >> 2, tg = lane & 3;
    const int qt = (int)(gridDim.x - 1 - blockIdx.x);
    const int h = blockIdx.y >> 2, b = blockIdx.y & 3;
    const int rw = wid * 16;

    const __half* Qg  = g_q + ((size_t)((b*NHEAD + h)*SEQ) + qt*128)*HDIM;
    const __half* Kg0 = g_k + (size_t)((b*NHEAD + h)*SEQ)*HDIM;
    const __half* Vg0 = g_v + (size_t)((b*NHEAD + h)*SEQ)*HDIM;
    const float*  Mb  = mask + ((size_t)h*SEQ + qt*128)*SEQ;

    // cp.async: physical smem row = crow; global source row = perm(crow)
    const int crow = tid >> 2, cc0 = tid & 3;
    const int p15 = crow & 15;
    const int l15 = (p15 < 8) ? ((p15 >> 1)*4 + (p15 & 1))
                              : (((p15 - 8) >> 1)*4 + 2 + (p15 & 1));
    const int lsrc = (crow & ~15) | l15;
    const size_t ksrc0 = __cvta_generic_to_global(Kg0 + (size_t)lsrc*HDIM);
    const size_t vsrc0 = __cvta_generic_to_global(Vg0 + (size_t)lsrc*HDIM);
    const uint32_t kdst0 = sb + crow*KVW*4;
    const uint32_t vdst0 = sb + (VS_BASE + crow*KVW)*4;

    #define KV_ISSUE(kt, st) do { \
        size_t ks_ = ksrc0 + (size_t)(kt)*64*HDIM*2; \
        size_t vs_ = vsrc0 + (size_t)(kt)*64*HDIM*2; \
        uint32_t kd_ = kdst0 + (st)*KV_STAGE*4; \
        uint32_t vd_ = vdst0 + (st)*KV_STAGE*4; \
        _Pragma("unroll") \
        for (int j_ = 0; j_ < 2; j_++) { \
            CP16(kd_ + (cc0 + 4*j_)*16, ks_ + (cc0 + 4*j_)*16); \
            CP16(vd_ + (cc0 + 4*j_)*16, vs_ + (cc0 + 4*j_)*16); \
        } \
        CP_COMMIT(); \
    } while (0)

    KV_ISSUE(0, 0);

    uint32_t qa[4][4];
    {
        const uint32_t* q0 = (const uint32_t*)(Qg + (size_t)(rw+g)*HDIM);
        const uint32_t* q1 = (const uint32_t*)(Qg + (size_t)(rw+8+g)*HDIM);
        #pragma unroll
        for (int kk = 0; kk < 4; kk++) {
            qa[kk][0] = q0[kk*8 + tg];
            qa[kk][1] = q1[kk*8 + tg];
            qa[kk][2] = q0[kk*8 + tg + 4];
            qa[kk][3] = q1[kk*8 + tg + 4];
        }
    }

    const int kRow = (lane & 7) + ((lane >> 4) & 1) * 8;
    const int kWof = ((lane >> 3) & 1) * 4;
    const int vRow = (lane & 7) + ((lane >> 3) & 1) * 8;
    const int vWof = (lane >> 4) * 4;

    float o[8][4];
    #pragma unroll
    for (int nt = 0; nt < 8; nt++)
        #pragma unroll
        for (int e = 0; e < 4; e++) o[nt][e] = 0.f;
    float m0 = -FLT_MAX, m1 = -FLT_MAX, l0 = 0.f, l1 = 0.f;

    const int ktEnd = 2*qt + 1;
    for (int kt = 0; kt <= ktEnd; kt++) {
        // mask -> S accumulators via LDG.128 (4 consecutive logical cols/thread)
        float s[8][4];
        const float* M0 = Mb + (size_t)(rw+g)*SEQ + kt*64;
        const float* M1 = M0 + (size_t)8*SEQ;
        #pragma unroll
        for (int ntp = 0; ntp < 4; ntp++) {
            float4 u = *(const float4*)(M0 + ntp*16 + tg*4);
            float4 w = *(const float4*)(M1 + ntp*16 + tg*4);
            s[2*ntp  ][0] = u.x; s[2*ntp  ][1] = u.y;
            s[2*ntp+1][0] = u.z; s[2*ntp+1][1] = u.w;
            s[2*ntp  ][2] = w.x; s[2*ntp  ][3] = w.y;
            s[2*ntp+1][2] = w.z; s[2*ntp+1][3] = w.w;
        }

        CP_WAIT0();
        __syncthreads();
        if (kt < ktEnd) KV_ISSUE(kt + 1, (kt + 1) & 1);

        const uint32_t kbase = sb + ((kt & 1)*KV_STAGE)*4;
        const uint32_t vbase = sb + (VS_BASE + (kt & 1)*KV_STAGE)*4;

        #pragma unroll
        for (int ntp = 0; ntp < 4; ntp++) {
            #pragma unroll
            for (int kk = 0; kk < 4; kk++) {
                uint32_t r0, r1, r2, r3;
                uint32_t ka = kbase + ((ntp*16 + kRow)*KVW + kk*8 + kWof)*4;
                LDSM_X4(r0, r1, r2, r3, ka);
                mma16(s[2*ntp  ], qa[kk][0],qa[kk][1],qa[kk][2],qa[kk][3], r0, r1);
                mma16(s[2*ntp+1], qa[kk][0],qa[kk][1],qa[kk][2],qa[kk][3], r2, r3);
            }
        }

        float rm0 = -FLT_MAX, rm1 = -FLT_MAX;
        #pragma unroll
        for (int nt = 0; nt < 8; nt++) {
            rm0 = fmaxf(rm0, fmaxf(s[nt][0], s[nt][1]));
            rm1 = fmaxf(rm1, fmaxf(s[nt][2], s[nt][3]));
        }
        rm0 = fmaxf(rm0, __shfl_xor_sync(0xffffffffu, rm0, 1));
        rm0 = fmaxf(rm0, __shfl_xor_sync(0xffffffffu, rm0, 2));
        rm1 = fmaxf(rm1, __shfl_xor_sync(0xffffffffu, rm1, 1));
        rm1 = fmaxf(rm1, __shfl_xor_sync(0xffffffffu, rm1, 2));

        float mn0 = fmaxf(m0, rm0), mn1 = fmaxf(m1, rm1);
        float f0 = __expf(m0 - mn0), f1 = __expf(m1 - mn1);
        m0 = mn0; m1 = mn1;

        float rs0 = 0.f, rs1 = 0.f;
        #pragma unroll
        for (int nt = 0; nt < 8; nt++) {
            s[nt][0] = __expf(s[nt][0] - mn0);
            s[nt][1] = __expf(s[nt][1] - mn0);
            s[nt][2] = __expf(s[nt][2] - mn1);
            s[nt][3] = __expf(s[nt][3] - mn1);
            rs0 += s[nt][0] + s[nt][1];
            rs1 += s[nt][2] + s[nt][3];
        }
        l0 = l0*f0 + rs0;
        l1 = l1*f1 + rs1;
        #pragma unroll
        for (int nt = 0; nt < 8; nt++) {
            o[nt][0] *= f0; o[nt][1] *= f0;
            o[nt][2] *= f1; o[nt][3] *= f1;
        }

        #pragma unroll
        for (int kk = 0; kk < 4; kk++) {
            uint32_t a0 = h2pack(s[2*kk  ][0], s[2*kk  ][1]);
            uint32_t a1 = h2pack(s[2*kk  ][2], s[2*kk  ][3]);
            uint32_t a2 = h2pack(s[2*kk+1][0], s[2*kk+1][1]);
            uint32_t a3 = h2pack(s[2*kk+1][2], s[2*kk+1][3]);
            #pragma unroll
            for (int ntp = 0; ntp < 4; ntp++) {
                uint32_t r0, r1, r2, r3;
                uint32_t va = vbase + ((kk*16 + vRow)*KVW + ntp*8 + vWof)*4;
                LDSM_X4T(r0, r1, r2, r3, va);
                mma16(o[2*ntp  ], a0, a1, a2, a3, r0, r1);
                mma16(o[2*ntp+1], a0, a1, a2, a3, r2, r3);
            }
        }
    }

    l0 += __shfl_xor_sync(0xffffffffu, l0, 1);
    l0 += __shfl_xor_sync(0xffffffffu, l0, 2);
    l1 += __shfl_xor_sync(0xffffffffu, l1, 1);
    l1 += __shfl_xor_sync(0xffffffffu, l1, 2);
    float inv0 = 1.f / l0, inv1 = 1.f / l1;

    int r0 = qt*128 + rw + g, r1 = r0 + 8;
    __half* y0 = g_y + (size_t)(b*SEQ + r0)*CDIM + h*HDIM;
    __half* y1 = g_y + (size_t)(b*SEQ + r1)*CDIM + h*HDIM;
    #pragma unroll
    for (int nt = 0; nt < 8; nt++) {
        int c = nt*8 + tg*2;
        *(uint32_t*)(y0 + c) = h2pack(o[nt][0]*inv0, o[nt][1]*inv0);
        *(uint32_t*)(y1 + c) = h2pack(o[nt][2]*inv1, o[nt][3]*inv1);
    }
}

// ===================== host =================================================
extern "C" void kernel_launch(void* const* d_in, const int* in_sizes, int n_in,
                              void* d_out, int out_size) {
    const float* x      = (const float*)d_in[0];
    const float* mask   = (const float*)d_in[1];
    const float* W_attn = (const float*)d_in[2];
    const float* b_attn = (const float*)d_in[3];
    const float* W_proj = (const float*)d_in[4];
    const float* b_proj = (const float*)d_in[5];
    float* out = (float*)d_out;

    void *p_xh, *p_wah, *p_wph;
    cudaGetSymbolAddress(&p_xh,  g_xh);
    cudaGetSymbolAddress(&p_wah, g_wah);
    cudaGetSymbolAddress(&p_wph, g_wph);

    cudaFuncSetAttribute((const void*)flash_attn,
                         cudaFuncAttributeMaxDynamicSharedMemorySize, FLASH_SMEM);
    cudaFuncSetAttribute((const void*)qkv_gemm,
                         cudaFuncAttributeMaxDynamicSharedMemorySize, G_SMEM);
    cudaFuncSetAttribute((const void*)proj_gemm,
                         cudaFuncAttributeMaxDynamicSharedMemorySize, G_SMEM);

    // prep: fp16 conversions (x row-major; weights transposed to [n][k])
    f2h<<<(MROWS*CDIM/4)/256, 256>>>(x, (__half*)p_xh);
    transpose_h<<<dim3(CDIM3/32, CDIM/32), 256>>>(W_attn, (__half*)p_wah, CDIM, CDIM3);
    transpose_h<<<dim3(CDIM/32, CDIM/32), 256>>>(W_proj, (__half*)p_wph, CDIM, CDIM);

    dim3 g1(CDIM3/128, MROWS/128);     // 18 x 64
    qkv_gemm<<<g1, 256, G_SMEM>>>(b_attn);

    dim3 g2(SEQ/128, NHEAD*NB);        // 16 x 48 (h-major: mask L2 reuse over b)
    flash_attn<<<g2, 256, FLASH_SMEM>>>(mask);

    dim3 g3(CDIM/128, MROWS/128);      // 6 x 64
    proj_gemm<<<g3, 256, G_SMEM>>>(b_proj, out);
}